// round 13
// baseline (speedup 1.0000x reference)
#include <cuda_runtime.h>
#include <cuda_bf16.h>
#include <cstdint>

// Problem constants
#define BT     4
#define NP     2048
#define NODES  (BT*NP)        // 8192
#define HD     128
#define KN     32
#define NL     4
#define OUTD   6

// ---------------- scratch (device globals; no allocation allowed) ----------
__device__ float g_h    [NODES*HD];
__device__ float g_ab   [NODES*2*HD];
__device__ int   g_idx  [NODES*KN];
__device__ float g_dn   [NODES*KN];
__device__ float g_bbias[NL*2*HD];         // [b1 | 0]
__device__ float g_b2p  [NL*HD];           // K*b2 @ W3b + b3

// bf16 hi/lo chunk-swizzled B-tile images (one image = 64n x 128k = 8192 bf16 = 16KB)
__device__ __align__(16) __nv_bfloat16 g_B1h [NL*4*8192], g_B1l [NL*4*8192];   // [W1a|W1b]
__device__ __align__(16) __nv_bfloat16 g_B2ah[NL*2*8192], g_B2al[NL*2*8192];   // W3a
__device__ __align__(16) __nv_bfloat16 g_B2bh[NL*2*8192], g_B2bl[NL*2*8192];   // W2@W3b
__device__ __align__(16) __nv_bfloat16 g_B3h [NL*2*8192], g_B3l [NL*2*8192];   // W4

__device__ __forceinline__ float tanh_ap(float x) {
    float r; asm("tanh.approx.f32 %0, %1;" : "=f"(r) : "f"(x)); return r;
}
__device__ __forceinline__ float silu_f(float x) {
    float hx = 0.5f * x;
    return fmaf(hx, tanh_ap(hx), hx);
}
__device__ __forceinline__ uint32_t smem_u32(const void* p) {
    uint32_t a;
    asm("{ .reg .u64 t; cvta.to.shared.u64 t, %1; cvt.u32.u64 %0, t; }"
        : "=r"(a) : "l"(p));
    return a;
}
__device__ __forceinline__ uint32_t pack_bf2(__nv_bfloat16 lo, __nv_bfloat16 hi) {
    return (uint32_t)__bfloat16_as_ushort(lo) | ((uint32_t)__bfloat16_as_ushort(hi) << 16);
}
// byte offset of element (row r, bf16 col k) in a 64-row x 128-col tile,
// 256B/row, 16B chunks XOR-swizzled: chunk' = chunk ^ (r & 7)
__device__ __forceinline__ uint32_t tile_off(int r, int k) {
    uint32_t ch = (uint32_t)(k >> 3);
    return (uint32_t)r*256u + ((ch ^ (uint32_t)(r & 7)) << 4) + (uint32_t)(k & 7)*2u;
}
// pack fp32 pair -> hi/lo u32s
__device__ __forceinline__ void split2(float v0, float v1, uint32_t& hw, uint32_t& lw) {
    __nv_bfloat16 h0 = __float2bfloat16(v0), h1 = __float2bfloat16(v1);
    hw = pack_bf2(h0, h1);
    lw = pack_bf2(__float2bfloat16(v0 - __bfloat162float(h0)),
                  __float2bfloat16(v1 - __bfloat162float(h1)));
}

__device__ __forceinline__ void ldm4(uint32_t& r0, uint32_t& r1,
                                     uint32_t& r2, uint32_t& r3, uint32_t addr) {
    asm volatile("ldmatrix.sync.aligned.m8n8.x4.shared.b16 {%0,%1,%2,%3}, [%4];"
                 : "=r"(r0), "=r"(r1), "=r"(r2), "=r"(r3) : "r"(addr));
}
__device__ __forceinline__ void mma16816(float* c, uint32_t a0, uint32_t a1,
                                         uint32_t a2, uint32_t a3,
                                         uint32_t b0, uint32_t b1) {
    asm volatile(
        "mma.sync.aligned.m16n8k16.row.col.f32.bf16.bf16.f32 "
        "{%0,%1,%2,%3}, {%4,%5,%6,%7}, {%8,%9}, {%0,%1,%2,%3};"
        : "+f"(c[0]), "+f"(c[1]), "+f"(c[2]), "+f"(c[3])
        : "r"(a0), "r"(a1), "r"(a2), "r"(a3), "r"(b0), "r"(b1));
}

// smem layout for the HMMA kernels
#define SM_AH  0
#define SM_AL  16384
#define SM_BH0 32768
#define SM_BL0 49152
#define SM_BH1 65536
#define SM_BL1 81920
#define SMEM_TC 98304

// ---------------- embed ----------------------------------------------------
__global__ void embed_k(const float* __restrict__ x,
                        const float* __restrict__ ew,
                        const float* __restrict__ eb) {
    int t = blockIdx.x * blockDim.x + threadIdx.x;
    int node = t >> 7, c = t & 127;
    float acc = eb[c];
    acc += x[node*3+0] * ew[c];
    acc += x[node*3+1] * ew[HD + c];
    acc += x[node*3+2] * ew[2*HD + c];
    g_h[t] = acc;
}

// ---------------- KNN (known-good) ------------------------------------------
#define TOP4_INS(v, jj)                                                  \
    if ((v) < m4) {                                                      \
        if ((v) < m1)      { m4=m3;j4=j3; m3=m2;j3=j2; m2=m1;j2=j1; m1=(v);j1=(jj); } \
        else if ((v) < m2) { m4=m3;j4=j3; m3=m2;j3=j2; m2=(v);j2=(jj); } \
        else if ((v) < m3) { m4=m3;j4=j3; m3=(v);j3=(jj); }              \
        else               { m4=(v);j4=(jj); }                           \
    }

__global__ void __launch_bounds__(128) knn_k(const float* __restrict__ x) {
    __shared__ float sd[4][NP];
    const float FINF = __int_as_float(0x7f800000);
    int w = threadIdx.x >> 5, lane = threadIdx.x & 31;
    int node = blockIdx.x * 4 + w;
    int b = node >> 11;
    int i = node & (NP - 1);
    const float* xb = x + b * NP * 3;
    float xi0 = x[node*3+0], xi1 = x[node*3+1], xi2 = x[node*3+2];
    float* dist = sd[w];

    for (int jj = lane; jj < NP; jj += 32) {
        float dx = __fadd_rn(xi0, -xb[jj*3+0]);
        float dy = __fadd_rn(xi1, -xb[jj*3+1]);
        float dz = __fadd_rn(xi2, -xb[jj*3+2]);
        float dq = __fadd_rn(__fadd_rn(__fmul_rn(dx,dx), __fmul_rn(dy,dy)),
                             __fmul_rn(dz,dz));
        dist[jj] = (jj == i) ? FINF : dq;
    }
    __syncwarp();

    float m1=FINF, m2=FINF, m3=FINF, m4=FINF;
    int   j1=lane, j2=lane, j3=lane, j4=lane;
    #pragma unroll
    for (int tt = 0; tt < NP/32; tt++) {
        int jj = lane + (tt << 5);
        float v = dist[jj];
        TOP4_INS(v, jj);
    }

    for (int r = 0; r < KN; r++) {
        float bv = m1; int bj = j1;
        #pragma unroll
        for (int off = 16; off; off >>= 1) {
            float ov = __shfl_down_sync(0xffffffffu, bv, off);
            int   oj = __shfl_down_sync(0xffffffffu, bj, off);
            if (ov < bv) { bv = ov; bj = oj; }
        }
        bv = __shfl_sync(0xffffffffu, bv, 0);
        bj = __shfl_sync(0xffffffffu, bj, 0);
        if (lane == 0) {
            g_idx[node*KN + r] = b * NP + bj;
            g_dn [node*KN + r] = sqrtf(bv);
        }
        if ((bj & 31) == lane) {
            dist[bj] = FINF;
            m1=m2; j1=j2; m2=m3; j2=j3; m3=m4; j3=j4; m4=FINF; j4=lane;
            if (!(m1 < FINF)) {
                m1=m2=m3=m4=FINF; j1=j2=j3=j4=lane;
                #pragma unroll
                for (int tt = 0; tt < NP/32; tt++) {
                    int jj = lane + (tt << 5);
                    float v = dist[jj];
                    TOP4_INS(v, jj);
                }
            }
        }
    }
}

// ---------------- unified prep: all weight images + biases ------------------
// regions 0..9 per layer: B-tile images (w2p computed inline for regions 6-7).
// appended: bbias (NL*2*HD), b2p (NL*HD).
__global__ void prep2_k(const float* __restrict__ miw, const float* __restrict__ mib,
                        const float* __restrict__ mow, const float* __restrict__ mob,
                        const float* __restrict__ uiw, const float* __restrict__ uib,
                        const float* __restrict__ uow) {
    const int PER_L = 10*8192;
    const int TOTAL_IMG = NL*PER_L;
    int t = blockIdx.x * blockDim.x + threadIdx.x;
    if (t < TOTAL_IMG) {
        int l = t / PER_L, u = t % PER_L;
        int region = u / 8192;            // 0..9
        int e = u & 8191;
        int tile, n_local = e >> 7, k = e & 127;
        float src;
        __nv_bfloat16 *dh, *dl;
        if (region < 4) {                 // gemm1 B: [W1a|W1b] col n, row k of W1
            tile = region;
            int n = tile*64 + n_local;
            const float* W1 = miw + l*257*HD;
            src = (n < HD) ? W1[k*HD + n] : W1[(HD + k)*HD + (n - HD)];
            dh = g_B1h + (l*4 + tile)*8192; dl = g_B1l + (l*4 + tile)*8192;
        } else if (region < 6) {          // W3a
            tile = region - 4;
            int n = tile*64 + n_local;
            src = uiw[l*2*HD*HD + k*HD + n];
            dh = g_B2ah + (l*2 + tile)*8192; dl = g_B2al + (l*2 + tile)*8192;
        } else if (region < 8) {          // w2p[k][n] = sum_q W2[k][q]*W3b[q][n]
            tile = region - 6;
            int n = tile*64 + n_local;
            const float* W2  = mow + l*HD*HD;
            const float* W3b = uiw + l*2*HD*HD + HD*HD;
            float acc = 0.0f;
            #pragma unroll 8
            for (int q = 0; q < HD; q++) acc += W2[k*HD + q] * W3b[q*HD + n];
            src = acc;
            dh = g_B2bh + (l*2 + tile)*8192; dl = g_B2bl + (l*2 + tile)*8192;
        } else {                          // W4
            tile = region - 8;
            int n = tile*64 + n_local;
            src = uow[l*HD*HD + k*HD + n];
            dh = g_B3h + (l*2 + tile)*8192; dl = g_B3l + (l*2 + tile)*8192;
        }
        __nv_bfloat16 hi = __float2bfloat16(src);
        __nv_bfloat16 lo = __float2bfloat16(src - __bfloat162float(hi));
        uint32_t eoff = tile_off(n_local, k) >> 1;
        dh[eoff] = hi; dl[eoff] = lo;
        return;
    }
    int u = t - TOTAL_IMG;
    if (u < NL*2*HD) {                    // bbias = [b1 | 0]
        int l = u / (2*HD); int j = u % (2*HD);
        g_bbias[u] = (j < HD) ? mib[l*HD + j] : 0.0f;
        return;
    }
    u -= NL*2*HD;
    if (u < NL*HD) {                      // b2p = K*b2 @ W3b + b3
        int l = u / HD; int c = u % HD;
        const float* b2  = mob + l*HD;
        const float* W3b = uiw + l*2*HD*HD + HD*HD;
        float acc = uib[l*HD + c];
        #pragma unroll 8
        for (int k = 0; k < HD; k++) acc += (float)KN * b2[k] * W3b[k*HD + c];
        g_b2p[u] = acc;
        return;
    }
}

// ======== shared device helpers for the HMMA kernels ========================
__device__ __forceinline__ void stage_A(char* smem, const float* __restrict__ A,
                                        int rowBase, int tid) {
    #pragma unroll
    for (int i = 0; i < 8; i++) {
        int id = tid + 128*i;               // 1024 chunks
        int r = id >> 4, ch = id & 15;
        const float* src = A + (size_t)(rowBase + r)*HD + ch*8;
        float4 a0 = *(const float4*)(src);
        float4 a1 = *(const float4*)(src + 4);
        uint4 hv, lv;
        split2(a0.x, a0.y, hv.x, lv.x);
        split2(a0.z, a0.w, hv.y, lv.y);
        split2(a1.x, a1.y, hv.z, lv.z);
        split2(a1.z, a1.w, hv.w, lv.w);
        uint32_t off = (uint32_t)r*256u + (((uint32_t)ch ^ (uint32_t)(r & 7)) << 4);
        *(uint4*)(smem + SM_AH + off) = hv;
        *(uint4*)(smem + SM_AL + off) = lv;
    }
}
__device__ __forceinline__ void stage_B(char* smem,
                                        const __nv_bfloat16* __restrict__ Bh,
                                        const __nv_bfloat16* __restrict__ Bl,
                                        int tid) {
    #pragma unroll
    for (int i = 0; i < 8; i++) {
        int id = tid + 128*i;
        *(uint4*)(smem + SM_BH0 + id*16) = ((const uint4*)Bh)[id];
        *(uint4*)(smem + SM_BH1 + id*16) = ((const uint4*)(Bh + 8192))[id];
        *(uint4*)(smem + SM_BL0 + id*16) = ((const uint4*)Bl)[id];
        *(uint4*)(smem + SM_BL1 + id*16) = ((const uint4*)(Bl + 8192))[id];
    }
}
__device__ __forceinline__ void mma_pass(uint32_t sb, float acc[2][8][4],
                                         uint32_t aBase0, uint32_t aBase1,
                                         uint32_t sBH, uint32_t sBL,
                                         uint32_t sw, int lrow, int lkoff) {
    #pragma unroll
    for (int ks = 0; ks < 8; ks++) {
        uint32_t kc = (uint32_t)(ks*2 + lkoff);
        uint32_t koff = ((kc ^ sw) << 4);
        uint32_t ah[8], al[8];
        ldm4(ah[0], ah[1], ah[2], ah[3], sb + SM_AH + aBase0 + koff);
        ldm4(ah[4], ah[5], ah[6], ah[7], sb + SM_AH + aBase1 + koff);
        ldm4(al[0], al[1], al[2], al[3], sb + SM_AL + aBase0 + koff);
        ldm4(al[4], al[5], al[6], al[7], sb + SM_AL + aBase1 + koff);
        #pragma unroll
        for (int q = 0; q < 4; q++) {
            uint32_t bh[4], bl[4];
            uint32_t bBase = (uint32_t)(q*16 + lrow)*256u + koff;
            ldm4(bh[0], bh[1], bh[2], bh[3], sBH + bBase);
            ldm4(bl[0], bl[1], bl[2], bl[3], sBL + bBase);
            #pragma unroll
            for (int mi = 0; mi < 2; mi++) {
                uint32_t* a = ah + mi*4;
                uint32_t* c = al + mi*4;
                mma16816(acc[mi][2*q+0], a[0], a[1], a[2], a[3], bh[0], bh[2]);
                mma16816(acc[mi][2*q+1], a[0], a[1], a[2], a[3], bh[1], bh[3]);
                mma16816(acc[mi][2*q+0], a[0], a[1], a[2], a[3], bl[0], bl[2]);
                mma16816(acc[mi][2*q+1], a[0], a[1], a[2], a[3], bl[1], bl[3]);
                mma16816(acc[mi][2*q+0], c[0], c[1], c[2], c[3], bh[0], bh[2]);
                mma16816(acc[mi][2*q+1], c[0], c[1], c[2], c[3], bh[1], bh[3]);
            }
        }
    }
}

// ---------------- gemm1: ab = h @ [W1a|W1b] + [b1|0]  (BN=128) --------------
__global__ void __launch_bounds__(128) gemm_tc(
    const float* __restrict__ A0,
    const __nv_bfloat16* __restrict__ B0h, const __nv_bfloat16* __restrict__ B0l,
    const float* __restrict__ bias,
    float* __restrict__ C, int N)
{
    extern __shared__ char smem[];
    uint32_t sb = smem_u32(smem);
    const int tid  = threadIdx.x;
    const int wid  = tid >> 5, lane = tid & 31;
    const int rowBase = blockIdx.x * 64;
    const int colBase = blockIdx.y * 128;
    const int wm = (wid & 1) * 32, wn = (wid >> 1) * 64;

    float acc[2][8][4];
    #pragma unroll
    for (int mi = 0; mi < 2; mi++)
        #pragma unroll
        for (int ni = 0; ni < 8; ni++)
            #pragma unroll
            for (int q = 0; q < 4; q++) acc[mi][ni][q] = 0.0f;

    const int lrow  = lane & 15;
    const int lkoff = lane >> 4;
    const uint32_t sw = (uint32_t)(lrow & 7);
    const uint32_t aBase0 = (uint32_t)(wm + lrow)*256u;
    const uint32_t aBase1 = (uint32_t)(wm + 16 + lrow)*256u;
    const uint32_t sBH = sb + (wn ? SM_BH1 : SM_BH0);
    const uint32_t sBL = sb + (wn ? SM_BL1 : SM_BL0);

    stage_A(smem, A0, rowBase, tid);
    stage_B(smem, B0h + (blockIdx.y*2)*8192, B0l + (blockIdx.y*2)*8192, tid);
    __syncthreads();
    mma_pass(sb, acc, aBase0, aBase1, sBH, sBL, sw, lrow, lkoff);

    const int erow = lane >> 2;
    const int ecol = (lane & 3) * 2;
    #pragma unroll
    for (int mi = 0; mi < 2; mi++) {
        #pragma unroll
        for (int ni = 0; ni < 8; ni++) {
            int row = rowBase + wm + mi*16 + erow;
            int col = colBase + wn + ni*8 + ecol;
            float bx = bias[col], by = bias[col+1];
            *(float2*)(C + (size_t)row*N + col) =
                make_float2(acc[mi][ni][0] + bx, acc[mi][ni][1] + by);
            *(float2*)(C + (size_t)(row+8)*N + col) =
                make_float2(acc[mi][ni][2] + bx, acc[mi][ni][3] + by);
        }
    }
}

// ---------------- layer23: edge + gemm2 + gemm3 fused -----------------------
// h += silu(h@W3a + s@w2p + b2p) @ W4 + b4, where s is computed in-CTA from
// the neighbor gather (edge pass). grid (128,1): CTA owns 64 rows, 128 cols.
__global__ void __launch_bounds__(128) layer23_k(
    const float* __restrict__ Ah_, const float* __restrict__ miw, int l,
    const __nv_bfloat16* __restrict__ B2ah, const __nv_bfloat16* __restrict__ B2al,
    const __nv_bfloat16* __restrict__ B2bh, const __nv_bfloat16* __restrict__ B2bl,
    const __nv_bfloat16* __restrict__ B3h,  const __nv_bfloat16* __restrict__ B3l,
    const float* __restrict__ b2p, const float* __restrict__ b4,
    float* __restrict__ H)
{
    extern __shared__ char smem[];
    uint32_t sb = smem_u32(smem);
    const int tid  = threadIdx.x;
    const int wid  = tid >> 5, lane = tid & 31;
    const int rowBase = blockIdx.x * 64;
    const int wm = (wid & 1) * 32, wn = (wid >> 1) * 64;

    float acc[2][8][4];
    #pragma unroll
    for (int mi = 0; mi < 2; mi++)
        #pragma unroll
        for (int ni = 0; ni < 8; ni++)
            #pragma unroll
            for (int q = 0; q < 4; q++) acc[mi][ni][q] = 0.0f;

    const int lrow  = lane & 15;
    const int lkoff = lane >> 4;
    const uint32_t sw = (uint32_t)(lrow & 7);
    const uint32_t aBase0 = (uint32_t)(wm + lrow)*256u;
    const uint32_t aBase1 = (uint32_t)(wm + 16 + lrow)*256u;
    const uint32_t sBH = sb + (wn ? SM_BH1 : SM_BH0);
    const uint32_t sBL = sb + (wn ? SM_BL1 : SM_BL0);
    const int erow = lane >> 2;
    const int ecol = (lane & 3) * 2;

    // ---- pass 1: h @ W3a ----
    stage_A(smem, Ah_, rowBase, tid);
    stage_B(smem, B2ah, B2al, tid);
    __syncthreads();
    mma_pass(sb, acc, aBase0, aBase1, sBH, sBL, sw, lrow, lkoff);

    // ---- edge compute: s rows -> smem A (swizzled hi/lo) ----
    __syncthreads();                  // all warps done reading SM_AH/AL
    {
        const float* wcp = miw + l*257*HD + 256*HD;
        float4 wc = *(const float4*)(wcp + lane*4);
        #pragma unroll 2
        for (int rr = 0; rr < 16; rr++) {
            int r = wid*16 + rr;
            int node = rowBase + r;
            float4 ai = *(const float4*)(g_ab + (size_t)node*256 + lane*4);
            const int*   jrow = g_idx + node*KN;
            const float* drow = g_dn  + node*KN;
            float4 sa = make_float4(0.f, 0.f, 0.f, 0.f);
            #pragma unroll 8
            for (int k = 0; k < KN; k++) {
                int j = jrow[k];
                float d = drow[k];
                float4 bb = *(const float4*)(g_ab + (size_t)j*256 + 128 + lane*4);
                sa.x += silu_f(ai.x + bb.x + d*wc.x);
                sa.y += silu_f(ai.y + bb.y + d*wc.y);
                sa.z += silu_f(ai.z + bb.z + d*wc.z);
                sa.w += silu_f(ai.w + bb.w + d*wc.w);
            }
            uint32_t hw, lw;
            split2(sa.x, sa.y, hw, lw);
            uint32_t o = tile_off(r, lane*4);
            *(uint32_t*)(smem + SM_AH + o) = hw;
            *(uint32_t*)(smem + SM_AL + o) = lw;
            split2(sa.z, sa.w, hw, lw);
            o = tile_off(r, lane*4 + 2);
            *(uint32_t*)(smem + SM_AH + o) = hw;
            *(uint32_t*)(smem + SM_AL + o) = lw;
        }
    }
    // ---- pass 2: + s @ w2p ----
    stage_B(smem, B2bh, B2bl, tid);
    __syncthreads();
    mma_pass(sb, acc, aBase0, aBase1, sBH, sBL, sw, lrow, lkoff);

    // ---- mid epilogue: p2 = silu(acc + b2p) -> smem A ----
    __syncthreads();
    #pragma unroll
    for (int mi = 0; mi < 2; mi++) {
        #pragma unroll
        for (int ni = 0; ni < 8; ni++) {
            int rl0 = wm + mi*16 + erow;
            int col = wn + ni*8 + ecol;
            float bx = b2p[col], by = b2p[col+1];
            float v00 = silu_f(acc[mi][ni][0] + bx);
            float v01 = silu_f(acc[mi][ni][1] + by);
            float v10 = silu_f(acc[mi][ni][2] + bx);
            float v11 = silu_f(acc[mi][ni][3] + by);
            uint32_t hw, lw;
            split2(v00, v01, hw, lw);
            uint32_t o = tile_off(rl0, col);
            *(uint32_t*)(smem + SM_AH + o) = hw;
            *(uint32_t*)(smem + SM_AL + o) = lw;
            split2(v10, v11, hw, lw);
            o = tile_off(rl0 + 8, col);
            *(uint32_t*)(smem + SM_AH + o) = hw;
            *(uint32_t*)(smem + SM_AL + o) = lw;
            acc[mi][ni][0] = acc[mi][ni][1] = acc[mi][ni][2] = acc[mi][ni][3] = 0.0f;
        }
    }
    // ---- pass 3: p2 @ W4 ----
    stage_B(smem, B3h, B3l, tid);
    __syncthreads();
    mma_pass(sb, acc, aBase0, aBase1, sBH, sBL, sw, lrow, lkoff);

    // ---- final epilogue: h += . + b4 ----
    #pragma unroll
    for (int mi = 0; mi < 2; mi++) {
        #pragma unroll
        for (int ni = 0; ni < 8; ni++) {
            int row = rowBase + wm + mi*16 + erow;
            int col = wn + ni*8 + ecol;
            float bx = b4[col], by = b4[col+1];
            float* h0 = H + (size_t)row*HD + col;
            float* h1 = H + (size_t)(row+8)*HD + col;
            float2 e0 = *(float2*)h0;
            float2 e1 = *(float2*)h1;
            *(float2*)h0 = make_float2(acc[mi][ni][0] + bx + e0.x,
                                       acc[mi][ni][1] + by + e0.y);
            *(float2*)h1 = make_float2(acc[mi][ni][2] + bx + e1.x,
                                       acc[mi][ni][3] + by + e1.y);
        }
    }
}

// ---------------- final projection ------------------------------------------
__global__ void out_k(const float* __restrict__ ow, const float* __restrict__ ob,
                      float* __restrict__ out) {
    int t = blockIdx.x * blockDim.x + threadIdx.x;
    if (t >= NODES*OUTD) return;
    int node = t / OUTD, oc = t % OUTD;
    float acc = ob[oc];
    #pragma unroll 8
    for (int k = 0; k < HD; k++) acc += g_h[node*HD + k] * ow[k*OUTD + oc];
    out[t] = acc;
}

// ---------------------------------------------------------------------------
extern "C" void kernel_launch(void* const* d_in, const int* in_sizes, int n_in,
                              void* d_out, int out_size) {
    const float* x   = (const float*)d_in[0];
    const float* ew  = (const float*)d_in[1];
    const float* eb  = (const float*)d_in[2];
    const float* miw = (const float*)d_in[3];
    const float* mib = (const float*)d_in[4];
    const float* mow = (const float*)d_in[5];
    const float* mob = (const float*)d_in[6];
    const float* uiw = (const float*)d_in[7];
    const float* uib = (const float*)d_in[8];
    const float* uow = (const float*)d_in[9];
    const float* uob = (const float*)d_in[10];
    const float* ow  = (const float*)d_in[11];
    const float* ob  = (const float*)d_in[12];
    float* out = (float*)d_out;

    cudaFuncSetAttribute(gemm_tc,   cudaFuncAttributeMaxDynamicSharedMemorySize, SMEM_TC);
    cudaFuncSetAttribute(layer23_k, cudaFuncAttributeMaxDynamicSharedMemorySize, SMEM_TC);

    float *ph, *pab, *pbbias, *pb2p;
    __nv_bfloat16 *pB1h, *pB1l, *pB2ah, *pB2al, *pB2bh, *pB2bl, *pB3h, *pB3l;
    cudaGetSymbolAddress((void**)&ph,     g_h);
    cudaGetSymbolAddress((void**)&pab,    g_ab);
    cudaGetSymbolAddress((void**)&pbbias, g_bbias);
    cudaGetSymbolAddress((void**)&pb2p,   g_b2p);
    cudaGetSymbolAddress((void**)&pB1h,   g_B1h);
    cudaGetSymbolAddress((void**)&pB1l,   g_B1l);
    cudaGetSymbolAddress((void**)&pB2ah,  g_B2ah);
    cudaGetSymbolAddress((void**)&pB2al,  g_B2al);
    cudaGetSymbolAddress((void**)&pB2bh,  g_B2bh);
    cudaGetSymbolAddress((void**)&pB2bl,  g_B2bl);
    cudaGetSymbolAddress((void**)&pB3h,   g_B3h);
    cudaGetSymbolAddress((void**)&pB3l,   g_B3l);

    embed_k<<<NODES*HD/256, 256>>>(x, ew, eb);
    knn_k<<<NODES/4, 128>>>(x);
    {
        int total = NL*10*8192 + NL*2*HD + NL*HD;
        prep2_k<<<(total + 255)/256, 256>>>(miw, mib, mow, mob, uiw, uib, uow);
    }

    for (int l = 0; l < NL; l++) {
        // [a|bb] = h @ [W1a|W1b] + [b1|0]   (8192 x 256)
        gemm_tc<<<dim3(128, 2), 128, SMEM_TC>>>(
            ph, pB1h + l*4*8192, pB1l + l*4*8192,
            pbbias + l*2*HD, pab, 2*HD);
        // h += silu(h@W3a + s@w2p + b2p) @ W4 + b4, s computed in-CTA
        layer23_k<<<dim3(128, 1), 128, SMEM_TC>>>(
            ph, miw, l,
            pB2ah + l*2*8192, pB2al + l*2*8192,
            pB2bh + l*2*8192, pB2bl + l*2*8192,
            pB3h + l*2*8192,  pB3l + l*2*8192,
            pb2p + l*HD, uob + l*HD, ph);
    }
    out_k<<<(NODES*OUTD + 255)/256, 256>>>(ow, ob, out);
}

// round 14
// speedup vs baseline: 2.0428x; 2.0428x over previous
#include <cuda_runtime.h>
#include <cuda_bf16.h>
#include <cstdint>

// Problem constants
#define BT     4
#define NP     2048
#define NODES  (BT*NP)        // 8192
#define HD     128
#define KN     32
#define NL     4
#define OUTD   6

// ---------------- scratch (device globals; no allocation allowed) ----------
__device__ float g_h    [NODES*HD];
__device__ float g_ab   [NODES*2*HD];
__device__ float g_s    [NODES*HD];
__device__ int   g_idx  [NODES*KN];
__device__ float g_dn   [NODES*KN];
__device__ float g_bbias[NL*2*HD];         // [b1 | 0]
__device__ float g_b2p  [NL*HD];           // K*b2 @ W3b + b3

// bf16 hi/lo chunk-swizzled B-tile images (one image = 64n x 128k = 8192 bf16 = 16KB)
__device__ __align__(16) __nv_bfloat16 g_B1h [NL*4*8192], g_B1l [NL*4*8192];   // [W1a|W1b]
__device__ __align__(16) __nv_bfloat16 g_B2ah[NL*2*8192], g_B2al[NL*2*8192];   // W3a
__device__ __align__(16) __nv_bfloat16 g_B2bh[NL*2*8192], g_B2bl[NL*2*8192];   // W2@W3b
__device__ __align__(16) __nv_bfloat16 g_B3h [NL*2*8192], g_B3l [NL*2*8192];   // W4

__device__ __forceinline__ float tanh_ap(float x) {
    float r; asm("tanh.approx.f32 %0, %1;" : "=f"(r) : "f"(x)); return r;
}
__device__ __forceinline__ float silu_f(float x) {
    float hx = 0.5f * x;
    return fmaf(hx, tanh_ap(hx), hx);
}
__device__ __forceinline__ uint32_t smem_u32(const void* p) {
    uint32_t a;
    asm("{ .reg .u64 t; cvta.to.shared.u64 t, %1; cvt.u32.u64 %0, t; }"
        : "=r"(a) : "l"(p));
    return a;
}
__device__ __forceinline__ uint32_t pack_bf2(__nv_bfloat16 lo, __nv_bfloat16 hi) {
    return (uint32_t)__bfloat16_as_ushort(lo) | ((uint32_t)__bfloat16_as_ushort(hi) << 16);
}
// byte offset of element (row r, bf16 col k) in a 64-row x 128-col tile,
// 256B/row, 16B chunks XOR-swizzled: chunk' = chunk ^ (r & 7)
__device__ __forceinline__ uint32_t tile_off(int r, int k) {
    uint32_t ch = (uint32_t)(k >> 3);
    return (uint32_t)r*256u + ((ch ^ (uint32_t)(r & 7)) << 4) + (uint32_t)(k & 7)*2u;
}
// pack fp32 pair -> hi/lo u32s
__device__ __forceinline__ void split2(float v0, float v1, uint32_t& hw, uint32_t& lw) {
    __nv_bfloat16 h0 = __float2bfloat16(v0), h1 = __float2bfloat16(v1);
    hw = pack_bf2(h0, h1);
    lw = pack_bf2(__float2bfloat16(v0 - __bfloat162float(h0)),
                  __float2bfloat16(v1 - __bfloat162float(h1)));
}

__device__ __forceinline__ void ldm4(uint32_t& r0, uint32_t& r1,
                                     uint32_t& r2, uint32_t& r3, uint32_t addr) {
    asm volatile("ldmatrix.sync.aligned.m8n8.x4.shared.b16 {%0,%1,%2,%3}, [%4];"
                 : "=r"(r0), "=r"(r1), "=r"(r2), "=r"(r3) : "r"(addr));
}
__device__ __forceinline__ void mma16816(float* c, uint32_t a0, uint32_t a1,
                                         uint32_t a2, uint32_t a3,
                                         uint32_t b0, uint32_t b1) {
    asm volatile(
        "mma.sync.aligned.m16n8k16.row.col.f32.bf16.bf16.f32 "
        "{%0,%1,%2,%3}, {%4,%5,%6,%7}, {%8,%9}, {%0,%1,%2,%3};"
        : "+f"(c[0]), "+f"(c[1]), "+f"(c[2]), "+f"(c[3])
        : "r"(a0), "r"(a1), "r"(a2), "r"(a3), "r"(b0), "r"(b1));
}

// smem layout for the HMMA kernels
#define SM_AH  0
#define SM_AL  16384
#define SM_BH0 32768
#define SM_BL0 49152
#define SM_BH1 65536
#define SM_BL1 81920
#define SMEM_TC 98304

// ---------------- embed ----------------------------------------------------
__global__ void embed_k(const float* __restrict__ x,
                        const float* __restrict__ ew,
                        const float* __restrict__ eb) {
    int t = blockIdx.x * blockDim.x + threadIdx.x;
    int node = t >> 7, c = t & 127;
    float acc = eb[c];
    acc += x[node*3+0] * ew[c];
    acc += x[node*3+1] * ew[HD + c];
    acc += x[node*3+2] * ew[2*HD + c];
    g_h[t] = acc;
}

// ---------------- KNN (known-good) ------------------------------------------
#define TOP4_INS(v, jj)                                                  \
    if ((v) < m4) {                                                      \
        if ((v) < m1)      { m4=m3;j4=j3; m3=m2;j3=j2; m2=m1;j2=j1; m1=(v);j1=(jj); } \
        else if ((v) < m2) { m4=m3;j4=j3; m3=m2;j3=j2; m2=(v);j2=(jj); } \
        else if ((v) < m3) { m4=m3;j4=j3; m3=(v);j3=(jj); }              \
        else               { m4=(v);j4=(jj); }                           \
    }

__global__ void __launch_bounds__(128) knn_k(const float* __restrict__ x) {
    __shared__ float sd[4][NP];
    const float FINF = __int_as_float(0x7f800000);
    int w = threadIdx.x >> 5, lane = threadIdx.x & 31;
    int node = blockIdx.x * 4 + w;
    int b = node >> 11;
    int i = node & (NP - 1);
    const float* xb = x + b * NP * 3;
    float xi0 = x[node*3+0], xi1 = x[node*3+1], xi2 = x[node*3+2];
    float* dist = sd[w];

    for (int jj = lane; jj < NP; jj += 32) {
        float dx = __fadd_rn(xi0, -xb[jj*3+0]);
        float dy = __fadd_rn(xi1, -xb[jj*3+1]);
        float dz = __fadd_rn(xi2, -xb[jj*3+2]);
        float dq = __fadd_rn(__fadd_rn(__fmul_rn(dx,dx), __fmul_rn(dy,dy)),
                             __fmul_rn(dz,dz));
        dist[jj] = (jj == i) ? FINF : dq;
    }
    __syncwarp();

    float m1=FINF, m2=FINF, m3=FINF, m4=FINF;
    int   j1=lane, j2=lane, j3=lane, j4=lane;
    #pragma unroll
    for (int tt = 0; tt < NP/32; tt++) {
        int jj = lane + (tt << 5);
        float v = dist[jj];
        TOP4_INS(v, jj);
    }

    for (int r = 0; r < KN; r++) {
        float bv = m1; int bj = j1;
        #pragma unroll
        for (int off = 16; off; off >>= 1) {
            float ov = __shfl_down_sync(0xffffffffu, bv, off);
            int   oj = __shfl_down_sync(0xffffffffu, bj, off);
            if (ov < bv) { bv = ov; bj = oj; }
        }
        bv = __shfl_sync(0xffffffffu, bv, 0);
        bj = __shfl_sync(0xffffffffu, bj, 0);
        if (lane == 0) {
            g_idx[node*KN + r] = b * NP + bj;
            g_dn [node*KN + r] = sqrtf(bv);
        }
        if ((bj & 31) == lane) {
            dist[bj] = FINF;
            m1=m2; j1=j2; m2=m3; j2=j3; m3=m4; j3=j4; m4=FINF; j4=lane;
            if (!(m1 < FINF)) {
                m1=m2=m3=m4=FINF; j1=j2=j3=j4=lane;
                #pragma unroll
                for (int tt = 0; tt < NP/32; tt++) {
                    int jj = lane + (tt << 5);
                    float v = dist[jj];
                    TOP4_INS(v, jj);
                }
            }
        }
    }
}

// ---------------- unified prep: all weight images + biases ------------------
__global__ void prep2_k(const float* __restrict__ miw, const float* __restrict__ mib,
                        const float* __restrict__ mow, const float* __restrict__ mob,
                        const float* __restrict__ uiw, const float* __restrict__ uib,
                        const float* __restrict__ uow) {
    const int PER_L = 10*8192;
    const int TOTAL_IMG = NL*PER_L;
    int t = blockIdx.x * blockDim.x + threadIdx.x;
    if (t < TOTAL_IMG) {
        int l = t / PER_L, u = t % PER_L;
        int region = u / 8192;            // 0..9
        int e = u & 8191;
        int tile, n_local = e >> 7, k = e & 127;
        float src;
        __nv_bfloat16 *dh, *dl;
        if (region < 4) {                 // gemm1 B: [W1a|W1b] col n, row k of W1
            tile = region;
            int n = tile*64 + n_local;
            const float* W1 = miw + l*257*HD;
            src = (n < HD) ? W1[k*HD + n] : W1[(HD + k)*HD + (n - HD)];
            dh = g_B1h + (l*4 + tile)*8192; dl = g_B1l + (l*4 + tile)*8192;
        } else if (region < 6) {          // W3a
            tile = region - 4;
            int n = tile*64 + n_local;
            src = uiw[l*2*HD*HD + k*HD + n];
            dh = g_B2ah + (l*2 + tile)*8192; dl = g_B2al + (l*2 + tile)*8192;
        } else if (region < 8) {          // w2p[k][n] = sum_q W2[k][q]*W3b[q][n]
            tile = region - 6;
            int n = tile*64 + n_local;
            const float* W2  = mow + l*HD*HD;
            const float* W3b = uiw + l*2*HD*HD + HD*HD;
            float acc = 0.0f;
            #pragma unroll 8
            for (int q = 0; q < HD; q++) acc += W2[k*HD + q] * W3b[q*HD + n];
            src = acc;
            dh = g_B2bh + (l*2 + tile)*8192; dl = g_B2bl + (l*2 + tile)*8192;
        } else {                          // W4
            tile = region - 8;
            int n = tile*64 + n_local;
            src = uow[l*HD*HD + k*HD + n];
            dh = g_B3h + (l*2 + tile)*8192; dl = g_B3l + (l*2 + tile)*8192;
        }
        __nv_bfloat16 hi = __float2bfloat16(src);
        __nv_bfloat16 lo = __float2bfloat16(src - __bfloat162float(hi));
        uint32_t eoff = tile_off(n_local, k) >> 1;
        dh[eoff] = hi; dl[eoff] = lo;
        return;
    }
    int u = t - TOTAL_IMG;
    if (u < NL*2*HD) {                    // bbias = [b1 | 0]
        int l = u / (2*HD); int j = u % (2*HD);
        g_bbias[u] = (j < HD) ? mib[l*HD + j] : 0.0f;
        return;
    }
    u -= NL*2*HD;
    if (u < NL*HD) {                      // b2p = K*b2 @ W3b + b3
        int l = u / HD; int c = u % HD;
        const float* b2  = mob + l*HD;
        const float* W3b = uiw + l*2*HD*HD + HD*HD;
        float acc = uib[l*HD + c];
        #pragma unroll 8
        for (int k = 0; k < HD; k++) acc += (float)KN * b2[k] * W3b[k*HD + c];
        g_b2p[u] = acc;
        return;
    }
}

// ---------------- edge pass (standalone, 8192 blocks: full latency hiding) --
__global__ void __launch_bounds__(128) edge_k(const float* __restrict__ miw, int l) {
    int node = blockIdx.x;
    int c = threadIdx.x;
    __shared__ int   sj[KN];
    __shared__ float sdd[KN];
    if (c < KN) {
        sj[c]  = g_idx[node*KN + c];
        sdd[c] = g_dn [node*KN + c];
    }
    __syncthreads();
    float ai = g_ab[node*2*HD + c];
    float wc = miw[l*257*HD + 256*HD + c];
    float acc = 0.0f;
    #pragma unroll 8
    for (int k = 0; k < KN; k++) {
        int j = sj[k];
        float v = ai + g_ab[j*2*HD + HD + c] + sdd[k] * wc;
        acc += silu_f(v);
    }
    g_s[node*HD + c] = acc;
}

// ======== shared device helpers for the HMMA kernels (256 threads) ==========
__device__ __forceinline__ void stage_A(char* smem, const float* __restrict__ A,
                                        int rowBase, int tid) {
    #pragma unroll
    for (int i = 0; i < 4; i++) {
        int id = tid + 256*i;               // 1024 chunks
        int r = id >> 4, ch = id & 15;
        const float* src = A + (size_t)(rowBase + r)*HD + ch*8;
        float4 a0 = *(const float4*)(src);
        float4 a1 = *(const float4*)(src + 4);
        uint4 hv, lv;
        split2(a0.x, a0.y, hv.x, lv.x);
        split2(a0.z, a0.w, hv.y, lv.y);
        split2(a1.x, a1.y, hv.z, lv.z);
        split2(a1.z, a1.w, hv.w, lv.w);
        uint32_t off = (uint32_t)r*256u + (((uint32_t)ch ^ (uint32_t)(r & 7)) << 4);
        *(uint4*)(smem + SM_AH + off) = hv;
        *(uint4*)(smem + SM_AL + off) = lv;
    }
}
__device__ __forceinline__ void stage_B(char* smem,
                                        const __nv_bfloat16* __restrict__ Bh,
                                        const __nv_bfloat16* __restrict__ Bl,
                                        int tid) {
    #pragma unroll
    for (int i = 0; i < 4; i++) {
        int id = tid + 256*i;               // 1024 uint4 per image
        *(uint4*)(smem + SM_BH0 + id*16) = ((const uint4*)Bh)[id];
        *(uint4*)(smem + SM_BH1 + id*16) = ((const uint4*)(Bh + 8192))[id];
        *(uint4*)(smem + SM_BL0 + id*16) = ((const uint4*)Bl)[id];
        *(uint4*)(smem + SM_BL1 + id*16) = ((const uint4*)(Bl + 8192))[id];
    }
}
// one full K=128 MMA pass; warp = m16 x n64; acc[8][4]
__device__ __forceinline__ void mma_pass(uint32_t sb, float acc[8][4],
                                         uint32_t aBase,
                                         uint32_t sBH, uint32_t sBL,
                                         uint32_t sw, int lrow, int lkoff) {
    #pragma unroll
    for (int ks = 0; ks < 8; ks++) {
        uint32_t kc = (uint32_t)(ks*2 + lkoff);
        uint32_t koff = ((kc ^ sw) << 4);
        uint32_t ah[4], al[4];
        ldm4(ah[0], ah[1], ah[2], ah[3], sb + SM_AH + aBase + koff);
        ldm4(al[0], al[1], al[2], al[3], sb + SM_AL + aBase + koff);
        #pragma unroll
        for (int q = 0; q < 4; q++) {
            uint32_t bh[4], bl[4];
            uint32_t bBase = (uint32_t)(q*16 + lrow)*256u + koff;
            ldm4(bh[0], bh[1], bh[2], bh[3], sBH + bBase);
            ldm4(bl[0], bl[1], bl[2], bl[3], sBL + bBase);
            mma16816(acc[2*q+0], ah[0], ah[1], ah[2], ah[3], bh[0], bh[2]);
            mma16816(acc[2*q+1], ah[0], ah[1], ah[2], ah[3], bh[1], bh[3]);
            mma16816(acc[2*q+0], ah[0], ah[1], ah[2], ah[3], bl[0], bl[2]);
            mma16816(acc[2*q+1], ah[0], ah[1], ah[2], ah[3], bl[1], bl[3]);
            mma16816(acc[2*q+0], al[0], al[1], al[2], al[3], bh[0], bh[2]);
            mma16816(acc[2*q+1], al[0], al[1], al[2], al[3], bh[1], bh[3]);
        }
    }
}

// ---------------- gemm1: ab = h @ [W1a|W1b] + [b1|0]  (BN=128, 8 warps) -----
__global__ void __launch_bounds__(256) gemm_tc(
    const float* __restrict__ A0,
    const __nv_bfloat16* __restrict__ B0h, const __nv_bfloat16* __restrict__ B0l,
    const float* __restrict__ bias,
    float* __restrict__ C, int N)
{
    extern __shared__ char smem[];
    uint32_t sb = smem_u32(smem);
    const int tid  = threadIdx.x;
    const int wid  = tid >> 5, lane = tid & 31;
    const int rowBase = blockIdx.x * 64;
    const int colBase = blockIdx.y * 128;
    const int wm = (wid & 3) * 16, wn = (wid >> 2) * 64;

    float acc[8][4];
    #pragma unroll
    for (int ni = 0; ni < 8; ni++)
        #pragma unroll
        for (int q = 0; q < 4; q++) acc[ni][q] = 0.0f;

    const int lrow  = lane & 15;
    const int lkoff = lane >> 4;
    const uint32_t sw = (uint32_t)(lrow & 7);
    const uint32_t aBase = (uint32_t)(wm + lrow)*256u;
    const uint32_t sBH = sb + (wn ? SM_BH1 : SM_BH0);
    const uint32_t sBL = sb + (wn ? SM_BL1 : SM_BL0);

    stage_A(smem, A0, rowBase, tid);
    stage_B(smem, B0h + (blockIdx.y*2)*8192, B0l + (blockIdx.y*2)*8192, tid);
    __syncthreads();
    mma_pass(sb, acc, aBase, sBH, sBL, sw, lrow, lkoff);

    const int erow = lane >> 2;
    const int ecol = (lane & 3) * 2;
    #pragma unroll
    for (int ni = 0; ni < 8; ni++) {
        int row = rowBase + wm + erow;
        int col = colBase + wn + ni*8 + ecol;
        float bx = bias[col], by = bias[col+1];
        *(float2*)(C + (size_t)row*N + col) =
            make_float2(acc[ni][0] + bx, acc[ni][1] + by);
        *(float2*)(C + (size_t)(row+8)*N + col) =
            make_float2(acc[ni][2] + bx, acc[ni][3] + by);
    }
}

// ---------------- gemm23: h += silu(h@W3a + s@w2p + b2p) @ W4 + b4 ----------
// grid (128): CTA owns 64 rows, full 128-col width, 8 warps.
__global__ void __launch_bounds__(256) gemm23_k(
    const float* __restrict__ Ah_, const float* __restrict__ As_,
    const __nv_bfloat16* __restrict__ B2ah, const __nv_bfloat16* __restrict__ B2al,
    const __nv_bfloat16* __restrict__ B2bh, const __nv_bfloat16* __restrict__ B2bl,
    const __nv_bfloat16* __restrict__ B3h,  const __nv_bfloat16* __restrict__ B3l,
    const float* __restrict__ b2p, const float* __restrict__ b4,
    float* __restrict__ H)
{
    extern __shared__ char smem[];
    uint32_t sb = smem_u32(smem);
    const int tid  = threadIdx.x;
    const int wid  = tid >> 5, lane = tid & 31;
    const int rowBase = blockIdx.x * 64;
    const int wm = (wid & 3) * 16, wn = (wid >> 2) * 64;

    float acc[8][4];
    #pragma unroll
    for (int ni = 0; ni < 8; ni++)
        #pragma unroll
        for (int q = 0; q < 4; q++) acc[ni][q] = 0.0f;

    const int lrow  = lane & 15;
    const int lkoff = lane >> 4;
    const uint32_t sw = (uint32_t)(lrow & 7);
    const uint32_t aBase = (uint32_t)(wm + lrow)*256u;
    const uint32_t sBH = sb + (wn ? SM_BH1 : SM_BH0);
    const uint32_t sBL = sb + (wn ? SM_BL1 : SM_BL0);
    const int erow = lane >> 2;
    const int ecol = (lane & 3) * 2;

    // ---- pass 1: h @ W3a ----
    stage_A(smem, Ah_, rowBase, tid);
    stage_B(smem, B2ah, B2al, tid);
    __syncthreads();
    mma_pass(sb, acc, aBase, sBH, sBL, sw, lrow, lkoff);

    // ---- pass 2: + s @ w2p ----
    __syncthreads();
    stage_A(smem, As_, rowBase, tid);
    stage_B(smem, B2bh, B2bl, tid);
    __syncthreads();
    mma_pass(sb, acc, aBase, sBH, sBL, sw, lrow, lkoff);

    // ---- mid epilogue: p2 = silu(acc + b2p) -> smem A (swizzled hi/lo) ----
    __syncthreads();                  // all warps done reading SM_AH/AL
    #pragma unroll
    for (int ni = 0; ni < 8; ni++) {
        int rl0 = wm + erow;                  // tile-local rows
        int col = wn + ni*8 + ecol;
        float bx = b2p[col], by = b2p[col+1];
        float v00 = silu_f(acc[ni][0] + bx);
        float v01 = silu_f(acc[ni][1] + by);
        float v10 = silu_f(acc[ni][2] + bx);
        float v11 = silu_f(acc[ni][3] + by);
        uint32_t hw, lw;
        split2(v00, v01, hw, lw);
        uint32_t o = tile_off(rl0, col);
        *(uint32_t*)(smem + SM_AH + o) = hw;
        *(uint32_t*)(smem + SM_AL + o) = lw;
        split2(v10, v11, hw, lw);
        o = tile_off(rl0 + 8, col);
        *(uint32_t*)(smem + SM_AH + o) = hw;
        *(uint32_t*)(smem + SM_AL + o) = lw;
        acc[ni][0] = acc[ni][1] = acc[ni][2] = acc[ni][3] = 0.0f;
    }
    // ---- pass 3: p2 @ W4 ----
    stage_B(smem, B3h, B3l, tid);
    __syncthreads();                  // orders p2 writes + B3 staging before reads
    mma_pass(sb, acc, aBase, sBH, sBL, sw, lrow, lkoff);

    // ---- final epilogue: h += . + b4 ----
    #pragma unroll
    for (int ni = 0; ni < 8; ni++) {
        int row = rowBase + wm + erow;
        int col = wn + ni*8 + ecol;
        float bx = b4[col], by = b4[col+1];
        float* h0 = H + (size_t)row*HD + col;
        float* h1 = H + (size_t)(row+8)*HD + col;
        float2 e0 = *(float2*)h0;
        float2 e1 = *(float2*)h1;
        *(float2*)h0 = make_float2(acc[ni][0] + bx + e0.x,
                                   acc[ni][1] + by + e0.y);
        *(float2*)h1 = make_float2(acc[ni][2] + bx + e1.x,
                                   acc[ni][3] + by + e1.y);
    }
}

// ---------------- final projection ------------------------------------------
__global__ void out_k(const float* __restrict__ ow, const float* __restrict__ ob,
                      float* __restrict__ out) {
    int t = blockIdx.x * blockDim.x + threadIdx.x;
    if (t >= NODES*OUTD) return;
    int node = t / OUTD, oc = t % OUTD;
    float acc = ob[oc];
    #pragma unroll 8
    for (int k = 0; k < HD; k++) acc += g_h[node*HD + k] * ow[k*OUTD + oc];
    out[t] = acc;
}

// ---------------------------------------------------------------------------
extern "C" void kernel_launch(void* const* d_in, const int* in_sizes, int n_in,
                              void* d_out, int out_size) {
    const float* x   = (const float*)d_in[0];
    const float* ew  = (const float*)d_in[1];
    const float* eb  = (const float*)d_in[2];
    const float* miw = (const float*)d_in[3];
    const float* mib = (const float*)d_in[4];
    const float* mow = (const float*)d_in[5];
    const float* mob = (const float*)d_in[6];
    const float* uiw = (const float*)d_in[7];
    const float* uib = (const float*)d_in[8];
    const float* uow = (const float*)d_in[9];
    const float* uob = (const float*)d_in[10];
    const float* ow  = (const float*)d_in[11];
    const float* ob  = (const float*)d_in[12];
    float* out = (float*)d_out;

    cudaFuncSetAttribute(gemm_tc,  cudaFuncAttributeMaxDynamicSharedMemorySize, SMEM_TC);
    cudaFuncSetAttribute(gemm23_k, cudaFuncAttributeMaxDynamicSharedMemorySize, SMEM_TC);

    float *ph, *pab, *ps, *pbbias, *pb2p;
    __nv_bfloat16 *pB1h, *pB1l, *pB2ah, *pB2al, *pB2bh, *pB2bl, *pB3h, *pB3l;
    cudaGetSymbolAddress((void**)&ph,     g_h);
    cudaGetSymbolAddress((void**)&pab,    g_ab);
    cudaGetSymbolAddress((void**)&ps,     g_s);
    cudaGetSymbolAddress((void**)&pbbias, g_bbias);
    cudaGetSymbolAddress((void**)&pb2p,   g_b2p);
    cudaGetSymbolAddress((void**)&pB1h,   g_B1h);
    cudaGetSymbolAddress((void**)&pB1l,   g_B1l);
    cudaGetSymbolAddress((void**)&pB2ah,  g_B2ah);
    cudaGetSymbolAddress((void**)&pB2al,  g_B2al);
    cudaGetSymbolAddress((void**)&pB2bh,  g_B2bh);
    cudaGetSymbolAddress((void**)&pB2bl,  g_B2bl);
    cudaGetSymbolAddress((void**)&pB3h,   g_B3h);
    cudaGetSymbolAddress((void**)&pB3l,   g_B3l);

    embed_k<<<NODES*HD/256, 256>>>(x, ew, eb);
    knn_k<<<NODES/4, 128>>>(x);
    {
        int total = NL*10*8192 + NL*2*HD + NL*HD;
        prep2_k<<<(total + 255)/256, 256>>>(miw, mib, mow, mob, uiw, uib, uow);
    }

    for (int l = 0; l < NL; l++) {
        // [a|bb] = h @ [W1a|W1b] + [b1|0]   (8192 x 256)
        gemm_tc<<<dim3(128, 2), 256, SMEM_TC>>>(
            ph, pB1h + l*4*8192, pB1l + l*4*8192,
            pbbias + l*2*HD, pab, 2*HD);
        // s_i = sum_k silu(a_i + bb_j + d*w1c)
        edge_k<<<NODES, 128>>>(miw, l);
        // h += silu(h@W3a + s@w2p + b2p) @ W4 + b4   (fused gemm2+3)
        gemm23_k<<<dim3(128, 1), 256, SMEM_TC>>>(
            ph, ps,
            pB2ah + l*2*8192, pB2al + l*2*8192,
            pB2bh + l*2*8192, pB2bl + l*2*8192,
            pB3h + l*2*8192,  pB3l + l*2*8192,
            pb2p + l*HD, uob + l*HD, ph);
    }
    out_k<<<(NODES*OUTD + 255)/256, 256>>>(ow, ob, out);
}

// round 15
// speedup vs baseline: 2.0765x; 1.0165x over previous
#include <cuda_runtime.h>
#include <cuda_bf16.h>
#include <cstdint>

// Problem constants
#define BT     4
#define NP     2048
#define NODES  (BT*NP)        // 8192
#define HD     128
#define KN     32
#define NL     4
#define OUTD   6

// ---------------- scratch (device globals; no allocation allowed) ----------
__device__ float g_h    [NODES*HD];
__device__ float g_ab   [NODES*2*HD];
__device__ float g_s    [NODES*HD];
__device__ int   g_idx  [NODES*KN];
__device__ float g_dn   [NODES*KN];
__device__ float g_bbias[NL*2*HD];         // [b1 | 0]
__device__ float g_b2p  [NL*HD];           // K*b2 @ W3b + b3

// bf16 hi/lo chunk-swizzled B-tile images (one image = 64n x 128k = 8192 bf16 = 16KB)
__device__ __align__(16) __nv_bfloat16 g_B1h [NL*4*8192], g_B1l [NL*4*8192];   // [W1a|W1b]
__device__ __align__(16) __nv_bfloat16 g_B2ah[NL*2*8192], g_B2al[NL*2*8192];   // W3a
__device__ __align__(16) __nv_bfloat16 g_B2bh[NL*2*8192], g_B2bl[NL*2*8192];   // W2@W3b
__device__ __align__(16) __nv_bfloat16 g_B3h [NL*2*8192], g_B3l [NL*2*8192];   // W4

__device__ __forceinline__ float tanh_ap(float x) {
    float r; asm("tanh.approx.f32 %0, %1;" : "=f"(r) : "f"(x)); return r;
}
__device__ __forceinline__ float silu_f(float x) {
    float hx = 0.5f * x;
    return fmaf(hx, tanh_ap(hx), hx);
}
__device__ __forceinline__ uint32_t smem_u32(const void* p) {
    uint32_t a;
    asm("{ .reg .u64 t; cvta.to.shared.u64 t, %1; cvt.u32.u64 %0, t; }"
        : "=r"(a) : "l"(p));
    return a;
}
__device__ __forceinline__ uint32_t pack_bf2(__nv_bfloat16 lo, __nv_bfloat16 hi) {
    return (uint32_t)__bfloat16_as_ushort(lo) | ((uint32_t)__bfloat16_as_ushort(hi) << 16);
}
// byte offset of element (row r, bf16 col k) in a 64-row x 128-col tile,
// 256B/row, 16B chunks XOR-swizzled: chunk' = chunk ^ (r & 7)
__device__ __forceinline__ uint32_t tile_off(int r, int k) {
    uint32_t ch = (uint32_t)(k >> 3);
    return (uint32_t)r*256u + ((ch ^ (uint32_t)(r & 7)) << 4) + (uint32_t)(k & 7)*2u;
}
// pack fp32 pair -> hi/lo u32s
__device__ __forceinline__ void split2(float v0, float v1, uint32_t& hw, uint32_t& lw) {
    __nv_bfloat16 h0 = __float2bfloat16(v0), h1 = __float2bfloat16(v1);
    hw = pack_bf2(h0, h1);
    lw = pack_bf2(__float2bfloat16(v0 - __bfloat162float(h0)),
                  __float2bfloat16(v1 - __bfloat162float(h1)));
}

__device__ __forceinline__ void ldm4(uint32_t& r0, uint32_t& r1,
                                     uint32_t& r2, uint32_t& r3, uint32_t addr) {
    asm volatile("ldmatrix.sync.aligned.m8n8.x4.shared.b16 {%0,%1,%2,%3}, [%4];"
                 : "=r"(r0), "=r"(r1), "=r"(r2), "=r"(r3) : "r"(addr));
}
__device__ __forceinline__ void mma16816(float* c, uint32_t a0, uint32_t a1,
                                         uint32_t a2, uint32_t a3,
                                         uint32_t b0, uint32_t b1) {
    asm volatile(
        "mma.sync.aligned.m16n8k16.row.col.f32.bf16.bf16.f32 "
        "{%0,%1,%2,%3}, {%4,%5,%6,%7}, {%8,%9}, {%0,%1,%2,%3};"
        : "+f"(c[0]), "+f"(c[1]), "+f"(c[2]), "+f"(c[3])
        : "r"(a0), "r"(a1), "r"(a2), "r"(a3), "r"(b0), "r"(b1));
}

// smem layout for the HMMA kernels
#define SM_AH  0
#define SM_AL  16384
#define SM_BH0 32768
#define SM_BL0 49152
#define SM_BH1 65536
#define SM_BL1 81920
#define SMEM_TC 98304

// ---------------- embed ----------------------------------------------------
__global__ void embed_k(const float* __restrict__ x,
                        const float* __restrict__ ew,
                        const float* __restrict__ eb) {
    int t = blockIdx.x * blockDim.x + threadIdx.x;
    int node = t >> 7, c = t & 127;
    float acc = eb[c];
    acc += x[node*3+0] * ew[c];
    acc += x[node*3+1] * ew[HD + c];
    acc += x[node*3+2] * ew[2*HD + c];
    g_h[t] = acc;
}

// ---------------- KNN (known-good) ------------------------------------------
#define TOP4_INS(v, jj)                                                  \
    if ((v) < m4) {                                                      \
        if ((v) < m1)      { m4=m3;j4=j3; m3=m2;j3=j2; m2=m1;j2=j1; m1=(v);j1=(jj); } \
        else if ((v) < m2) { m4=m3;j4=j3; m3=m2;j3=j2; m2=(v);j2=(jj); } \
        else if ((v) < m3) { m4=m3;j4=j3; m3=(v);j3=(jj); }              \
        else               { m4=(v);j4=(jj); }                           \
    }

__global__ void __launch_bounds__(128) knn_k(const float* __restrict__ x) {
    __shared__ float sd[4][NP];
    const float FINF = __int_as_float(0x7f800000);
    int w = threadIdx.x >> 5, lane = threadIdx.x & 31;
    int node = blockIdx.x * 4 + w;
    int b = node >> 11;
    int i = node & (NP - 1);
    const float* xb = x + b * NP * 3;
    float xi0 = x[node*3+0], xi1 = x[node*3+1], xi2 = x[node*3+2];
    float* dist = sd[w];

    for (int jj = lane; jj < NP; jj += 32) {
        float dx = __fadd_rn(xi0, -xb[jj*3+0]);
        float dy = __fadd_rn(xi1, -xb[jj*3+1]);
        float dz = __fadd_rn(xi2, -xb[jj*3+2]);
        float dq = __fadd_rn(__fadd_rn(__fmul_rn(dx,dx), __fmul_rn(dy,dy)),
                             __fmul_rn(dz,dz));
        dist[jj] = (jj == i) ? FINF : dq;
    }
    __syncwarp();

    float m1=FINF, m2=FINF, m3=FINF, m4=FINF;
    int   j1=lane, j2=lane, j3=lane, j4=lane;
    #pragma unroll
    for (int tt = 0; tt < NP/32; tt++) {
        int jj = lane + (tt << 5);
        float v = dist[jj];
        TOP4_INS(v, jj);
    }

    for (int r = 0; r < KN; r++) {
        float bv = m1; int bj = j1;
        #pragma unroll
        for (int off = 16; off; off >>= 1) {
            float ov = __shfl_down_sync(0xffffffffu, bv, off);
            int   oj = __shfl_down_sync(0xffffffffu, bj, off);
            if (ov < bv) { bv = ov; bj = oj; }
        }
        bv = __shfl_sync(0xffffffffu, bv, 0);
        bj = __shfl_sync(0xffffffffu, bj, 0);
        if (lane == 0) {
            g_idx[node*KN + r] = b * NP + bj;
            g_dn [node*KN + r] = sqrtf(bv);
        }
        if ((bj & 31) == lane) {
            dist[bj] = FINF;
            m1=m2; j1=j2; m2=m3; j2=j3; m3=m4; j3=j4; m4=FINF; j4=lane;
            if (!(m1 < FINF)) {
                m1=m2=m3=m4=FINF; j1=j2=j3=j4=lane;
                #pragma unroll
                for (int tt = 0; tt < NP/32; tt++) {
                    int jj = lane + (tt << 5);
                    float v = dist[jj];
                    TOP4_INS(v, jj);
                }
            }
        }
    }
}

// ---------------- unified prep: all weight images + biases ------------------
// regions 0..9 per layer: B-tile images (w2p computed inline for regions 6-7).
// appended: bbias (NL*2*HD), b2p (NL*HD).  (proven in R13/R14, same rel_err)
__global__ void prep2_k(const float* __restrict__ miw, const float* __restrict__ mib,
                        const float* __restrict__ mow, const float* __restrict__ mob,
                        const float* __restrict__ uiw, const float* __restrict__ uib,
                        const float* __restrict__ uow) {
    const int PER_L = 10*8192;
    const int TOTAL_IMG = NL*PER_L;
    int t = blockIdx.x * blockDim.x + threadIdx.x;
    if (t < TOTAL_IMG) {
        int l = t / PER_L, u = t % PER_L;
        int region = u / 8192;            // 0..9
        int e = u & 8191;
        int tile, n_local = e >> 7, k = e & 127;
        float src;
        __nv_bfloat16 *dh, *dl;
        if (region < 4) {                 // gemm1 B: [W1a|W1b] col n, row k of W1
            tile = region;
            int n = tile*64 + n_local;
            const float* W1 = miw + l*257*HD;
            src = (n < HD) ? W1[k*HD + n] : W1[(HD + k)*HD + (n - HD)];
            dh = g_B1h + (l*4 + tile)*8192; dl = g_B1l + (l*4 + tile)*8192;
        } else if (region < 6) {          // W3a
            tile = region - 4;
            int n = tile*64 + n_local;
            src = uiw[l*2*HD*HD + k*HD + n];
            dh = g_B2ah + (l*2 + tile)*8192; dl = g_B2al + (l*2 + tile)*8192;
        } else if (region < 8) {          // w2p[k][n] = sum_q W2[k][q]*W3b[q][n]
            tile = region - 6;
            int n = tile*64 + n_local;
            const float* W2  = mow + l*HD*HD;
            const float* W3b = uiw + l*2*HD*HD + HD*HD;
            float acc = 0.0f;
            #pragma unroll 8
            for (int q = 0; q < HD; q++) acc += W2[k*HD + q] * W3b[q*HD + n];
            src = acc;
            dh = g_B2bh + (l*2 + tile)*8192; dl = g_B2bl + (l*2 + tile)*8192;
        } else {                          // W4
            tile = region - 8;
            int n = tile*64 + n_local;
            src = uow[l*HD*HD + k*HD + n];
            dh = g_B3h + (l*2 + tile)*8192; dl = g_B3l + (l*2 + tile)*8192;
        }
        __nv_bfloat16 hi = __float2bfloat16(src);
        __nv_bfloat16 lo = __float2bfloat16(src - __bfloat162float(hi));
        uint32_t eoff = tile_off(n_local, k) >> 1;
        dh[eoff] = hi; dl[eoff] = lo;
        return;
    }
    int u = t - TOTAL_IMG;
    if (u < NL*2*HD) {                    // bbias = [b1 | 0]
        int l = u / (2*HD); int j = u % (2*HD);
        g_bbias[u] = (j < HD) ? mib[l*HD + j] : 0.0f;
        return;
    }
    u -= NL*2*HD;
    if (u < NL*HD) {                      // b2p = K*b2 @ W3b + b3
        int l = u / HD; int c = u % HD;
        const float* b2  = mob + l*HD;
        const float* W3b = uiw + l*2*HD*HD + HD*HD;
        float acc = uib[l*HD + c];
        #pragma unroll 8
        for (int k = 0; k < HD; k++) acc += (float)KN * b2[k] * W3b[k*HD + c];
        g_b2p[u] = acc;
        return;
    }
}

// ---------------- edge pass (standalone, 8192 blocks: full latency hiding) --
__global__ void __launch_bounds__(128) edge_k(const float* __restrict__ miw, int l) {
    int node = blockIdx.x;
    int c = threadIdx.x;
    __shared__ int   sj[KN];
    __shared__ float sdd[KN];
    if (c < KN) {
        sj[c]  = g_idx[node*KN + c];
        sdd[c] = g_dn [node*KN + c];
    }
    __syncthreads();
    float ai = g_ab[node*2*HD + c];
    float wc = miw[l*257*HD + 256*HD + c];
    float acc = 0.0f;
    #pragma unroll 8
    for (int k = 0; k < KN; k++) {
        int j = sj[k];
        float v = ai + g_ab[j*2*HD + HD + c] + sdd[k] * wc;
        acc += silu_f(v);
    }
    g_s[node*HD + c] = acc;
}

// ======== shared device helpers for the HMMA kernels (128 threads) ==========
__device__ __forceinline__ void stage_A(char* smem, const float* __restrict__ A,
                                        int rowBase, int tid) {
    #pragma unroll
    for (int i = 0; i < 8; i++) {
        int id = tid + 128*i;               // 1024 chunks
        int r = id >> 4, ch = id & 15;
        const float* src = A + (size_t)(rowBase + r)*HD + ch*8;
        float4 a0 = *(const float4*)(src);
        float4 a1 = *(const float4*)(src + 4);
        uint4 hv, lv;
        split2(a0.x, a0.y, hv.x, lv.x);
        split2(a0.z, a0.w, hv.y, lv.y);
        split2(a1.x, a1.y, hv.z, lv.z);
        split2(a1.z, a1.w, hv.w, lv.w);
        uint32_t off = (uint32_t)r*256u + (((uint32_t)ch ^ (uint32_t)(r & 7)) << 4);
        *(uint4*)(smem + SM_AH + off) = hv;
        *(uint4*)(smem + SM_AL + off) = lv;
    }
}
__device__ __forceinline__ void stage_B(char* smem,
                                        const __nv_bfloat16* __restrict__ Bh,
                                        const __nv_bfloat16* __restrict__ Bl,
                                        int tid) {
    #pragma unroll
    for (int i = 0; i < 8; i++) {
        int id = tid + 128*i;
        *(uint4*)(smem + SM_BH0 + id*16) = ((const uint4*)Bh)[id];
        *(uint4*)(smem + SM_BH1 + id*16) = ((const uint4*)(Bh + 8192))[id];
        *(uint4*)(smem + SM_BL0 + id*16) = ((const uint4*)Bl)[id];
        *(uint4*)(smem + SM_BL1 + id*16) = ((const uint4*)(Bl + 8192))[id];
    }
}
// one full K=128 MMA pass (3-term split), accumulating into acc[2][8][4]
__device__ __forceinline__ void mma_pass(uint32_t sb, float acc[2][8][4],
                                         uint32_t aBase0, uint32_t aBase1,
                                         uint32_t sBH, uint32_t sBL,
                                         uint32_t sw, int lrow, int lkoff) {
    #pragma unroll
    for (int ks = 0; ks < 8; ks++) {
        uint32_t kc = (uint32_t)(ks*2 + lkoff);
        uint32_t koff = ((kc ^ sw) << 4);
        uint32_t ah[8], al[8];
        ldm4(ah[0], ah[1], ah[2], ah[3], sb + SM_AH + aBase0 + koff);
        ldm4(ah[4], ah[5], ah[6], ah[7], sb + SM_AH + aBase1 + koff);
        ldm4(al[0], al[1], al[2], al[3], sb + SM_AL + aBase0 + koff);
        ldm4(al[4], al[5], al[6], al[7], sb + SM_AL + aBase1 + koff);
        #pragma unroll
        for (int q = 0; q < 4; q++) {
            uint32_t bh[4], bl[4];
            uint32_t bBase = (uint32_t)(q*16 + lrow)*256u + koff;
            ldm4(bh[0], bh[1], bh[2], bh[3], sBH + bBase);
            ldm4(bl[0], bl[1], bl[2], bl[3], sBL + bBase);
            #pragma unroll
            for (int mi = 0; mi < 2; mi++) {
                uint32_t* a = ah + mi*4;
                uint32_t* c = al + mi*4;
                mma16816(acc[mi][2*q+0], a[0], a[1], a[2], a[3], bh[0], bh[2]);
                mma16816(acc[mi][2*q+1], a[0], a[1], a[2], a[3], bh[1], bh[3]);
                mma16816(acc[mi][2*q+0], a[0], a[1], a[2], a[3], bl[0], bl[2]);
                mma16816(acc[mi][2*q+1], a[0], a[1], a[2], a[3], bl[1], bl[3]);
                mma16816(acc[mi][2*q+0], c[0], c[1], c[2], c[3], bh[0], bh[2]);
                mma16816(acc[mi][2*q+1], c[0], c[1], c[2], c[3], bh[1], bh[3]);
            }
        }
    }
}

// ---------------- gemm1: ab = h @ [W1a|W1b] + [b1|0]  (BN=128, 4 warps) -----
__global__ void __launch_bounds__(128) gemm_tc(
    const float* __restrict__ A0,
    const __nv_bfloat16* __restrict__ B0h, const __nv_bfloat16* __restrict__ B0l,
    const float* __restrict__ bias,
    float* __restrict__ C, int N)
{
    extern __shared__ char smem[];
    uint32_t sb = smem_u32(smem);
    const int tid  = threadIdx.x;
    const int wid  = tid >> 5, lane = tid & 31;
    const int rowBase = blockIdx.x * 64;
    const int colBase = blockIdx.y * 128;
    const int wm = (wid & 1) * 32, wn = (wid >> 1) * 64;

    float acc[2][8][4];
    #pragma unroll
    for (int mi = 0; mi < 2; mi++)
        #pragma unroll
        for (int ni = 0; ni < 8; ni++)
            #pragma unroll
            for (int q = 0; q < 4; q++) acc[mi][ni][q] = 0.0f;

    const int lrow  = lane & 15;
    const int lkoff = lane >> 4;
    const uint32_t sw = (uint32_t)(lrow & 7);
    const uint32_t aBase0 = (uint32_t)(wm + lrow)*256u;
    const uint32_t aBase1 = (uint32_t)(wm + 16 + lrow)*256u;
    const uint32_t sBH = sb + (wn ? SM_BH1 : SM_BH0);
    const uint32_t sBL = sb + (wn ? SM_BL1 : SM_BL0);

    stage_A(smem, A0, rowBase, tid);
    stage_B(smem, B0h + (blockIdx.y*2)*8192, B0l + (blockIdx.y*2)*8192, tid);
    __syncthreads();
    mma_pass(sb, acc, aBase0, aBase1, sBH, sBL, sw, lrow, lkoff);

    const int erow = lane >> 2;
    const int ecol = (lane & 3) * 2;
    #pragma unroll
    for (int mi = 0; mi < 2; mi++) {
        #pragma unroll
        for (int ni = 0; ni < 8; ni++) {
            int row = rowBase + wm + mi*16 + erow;
            int col = colBase + wn + ni*8 + ecol;
            float bx = bias[col], by = bias[col+1];
            *(float2*)(C + (size_t)row*N + col) =
                make_float2(acc[mi][ni][0] + bx, acc[mi][ni][1] + by);
            *(float2*)(C + (size_t)(row+8)*N + col) =
                make_float2(acc[mi][ni][2] + bx, acc[mi][ni][3] + by);
        }
    }
}

// ---------------- gemm23: h += silu(h@W3a + s@w2p + b2p) @ W4 + b4 ----------
// grid (128): CTA owns 64 rows, full 128-col width, 4 warps.
__global__ void __launch_bounds__(128) gemm23_k(
    const float* __restrict__ Ah_, const float* __restrict__ As_,
    const __nv_bfloat16* __restrict__ B2ah, const __nv_bfloat16* __restrict__ B2al,
    const __nv_bfloat16* __restrict__ B2bh, const __nv_bfloat16* __restrict__ B2bl,
    const __nv_bfloat16* __restrict__ B3h,  const __nv_bfloat16* __restrict__ B3l,
    const float* __restrict__ b2p, const float* __restrict__ b4,
    float* __restrict__ H)
{
    extern __shared__ char smem[];
    uint32_t sb = smem_u32(smem);
    const int tid  = threadIdx.x;
    const int wid  = tid >> 5, lane = tid & 31;
    const int rowBase = blockIdx.x * 64;
    const int wm = (wid & 1) * 32, wn = (wid >> 1) * 64;

    float acc[2][8][4];
    #pragma unroll
    for (int mi = 0; mi < 2; mi++)
        #pragma unroll
        for (int ni = 0; ni < 8; ni++)
            #pragma unroll
            for (int q = 0; q < 4; q++) acc[mi][ni][q] = 0.0f;

    const int lrow  = lane & 15;
    const int lkoff = lane >> 4;
    const uint32_t sw = (uint32_t)(lrow & 7);
    const uint32_t aBase0 = (uint32_t)(wm + lrow)*256u;
    const uint32_t aBase1 = (uint32_t)(wm + 16 + lrow)*256u;
    const uint32_t sBH = sb + (wn ? SM_BH1 : SM_BH0);
    const uint32_t sBL = sb + (wn ? SM_BL1 : SM_BL0);
    const int erow = lane >> 2;
    const int ecol = (lane & 3) * 2;

    // ---- pass 1: h @ W3a ----
    stage_A(smem, Ah_, rowBase, tid);
    stage_B(smem, B2ah, B2al, tid);
    __syncthreads();
    mma_pass(sb, acc, aBase0, aBase1, sBH, sBL, sw, lrow, lkoff);

    // ---- pass 2: + s @ w2p ----
    __syncthreads();
    stage_A(smem, As_, rowBase, tid);
    stage_B(smem, B2bh, B2bl, tid);
    __syncthreads();
    mma_pass(sb, acc, aBase0, aBase1, sBH, sBL, sw, lrow, lkoff);

    // ---- mid epilogue: p2 = silu(acc + b2p) -> smem A (swizzled hi/lo) ----
    __syncthreads();                  // all warps done reading SM_AH/AL
    #pragma unroll
    for (int mi = 0; mi < 2; mi++) {
        #pragma unroll
        for (int ni = 0; ni < 8; ni++) {
            int rl0 = wm + mi*16 + erow;
            int col = wn + ni*8 + ecol;
            float bx = b2p[col], by = b2p[col+1];
            float v00 = silu_f(acc[mi][ni][0] + bx);
            float v01 = silu_f(acc[mi][ni][1] + by);
            float v10 = silu_f(acc[mi][ni][2] + bx);
            float v11 = silu_f(acc[mi][ni][3] + by);
            uint32_t hw, lw;
            split2(v00, v01, hw, lw);
            uint32_t o = tile_off(rl0, col);
            *(uint32_t*)(smem + SM_AH + o) = hw;
            *(uint32_t*)(smem + SM_AL + o) = lw;
            split2(v10, v11, hw, lw);
            o = tile_off(rl0 + 8, col);
            *(uint32_t*)(smem + SM_AH + o) = hw;
            *(uint32_t*)(smem + SM_AL + o) = lw;
            acc[mi][ni][0] = acc[mi][ni][1] = acc[mi][ni][2] = acc[mi][ni][3] = 0.0f;
        }
    }
    // ---- pass 3: p2 @ W4 ----
    stage_B(smem, B3h, B3l, tid);
    __syncthreads();                  // orders p2 writes + B3 staging before reads
    mma_pass(sb, acc, aBase0, aBase1, sBH, sBL, sw, lrow, lkoff);

    // ---- final epilogue: h += . + b4 ----
    #pragma unroll
    for (int mi = 0; mi < 2; mi++) {
        #pragma unroll
        for (int ni = 0; ni < 8; ni++) {
            int row = rowBase + wm + mi*16 + erow;
            int col = wn + ni*8 + ecol;
            float bx = b4[col], by = b4[col+1];
            float* h0 = H + (size_t)row*HD + col;
            float* h1 = H + (size_t)(row+8)*HD + col;
            float2 e0 = *(float2*)h0;
            float2 e1 = *(float2*)h1;
            *(float2*)h0 = make_float2(acc[mi][ni][0] + bx + e0.x,
                                       acc[mi][ni][1] + by + e0.y);
            *(float2*)h1 = make_float2(acc[mi][ni][2] + bx + e1.x,
                                       acc[mi][ni][3] + by + e1.y);
        }
    }
}

// ---------------- final projection ------------------------------------------
__global__ void out_k(const float* __restrict__ ow, const float* __restrict__ ob,
                      float* __restrict__ out) {
    int t = blockIdx.x * blockDim.x + threadIdx.x;
    if (t >= NODES*OUTD) return;
    int node = t / OUTD, oc = t % OUTD;
    float acc = ob[oc];
    #pragma unroll 8
    for (int k = 0; k < HD; k++) acc += g_h[node*HD + k] * ow[k*OUTD + oc];
    out[t] = acc;
}

// ---------------------------------------------------------------------------
extern "C" void kernel_launch(void* const* d_in, const int* in_sizes, int n_in,
                              void* d_out, int out_size) {
    const float* x   = (const float*)d_in[0];
    const float* ew  = (const float*)d_in[1];
    const float* eb  = (const float*)d_in[2];
    const float* miw = (const float*)d_in[3];
    const float* mib = (const float*)d_in[4];
    const float* mow = (const float*)d_in[5];
    const float* mob = (const float*)d_in[6];
    const float* uiw = (const float*)d_in[7];
    const float* uib = (const float*)d_in[8];
    const float* uow = (const float*)d_in[9];
    const float* uob = (const float*)d_in[10];
    const float* ow  = (const float*)d_in[11];
    const float* ob  = (const float*)d_in[12];
    float* out = (float*)d_out;

    cudaFuncSetAttribute(gemm_tc,  cudaFuncAttributeMaxDynamicSharedMemorySize, SMEM_TC);
    cudaFuncSetAttribute(gemm23_k, cudaFuncAttributeMaxDynamicSharedMemorySize, SMEM_TC);

    float *ph, *pab, *ps, *pbbias, *pb2p;
    __nv_bfloat16 *pB1h, *pB1l, *pB2ah, *pB2al, *pB2bh, *pB2bl, *pB3h, *pB3l;
    cudaGetSymbolAddress((void**)&ph,     g_h);
    cudaGetSymbolAddress((void**)&pab,    g_ab);
    cudaGetSymbolAddress((void**)&ps,     g_s);
    cudaGetSymbolAddress((void**)&pbbias, g_bbias);
    cudaGetSymbolAddress((void**)&pb2p,   g_b2p);
    cudaGetSymbolAddress((void**)&pB1h,   g_B1h);
    cudaGetSymbolAddress((void**)&pB1l,   g_B1l);
    cudaGetSymbolAddress((void**)&pB2ah,  g_B2ah);
    cudaGetSymbolAddress((void**)&pB2al,  g_B2al);
    cudaGetSymbolAddress((void**)&pB2bh,  g_B2bh);
    cudaGetSymbolAddress((void**)&pB2bl,  g_B2bl);
    cudaGetSymbolAddress((void**)&pB3h,   g_B3h);
    cudaGetSymbolAddress((void**)&pB3l,   g_B3l);

    embed_k<<<NODES*HD/256, 256>>>(x, ew, eb);
    knn_k<<<NODES/4, 128>>>(x);
    {
        int total = NL*10*8192 + NL*2*HD + NL*HD;
        prep2_k<<<(total + 255)/256, 256>>>(miw, mib, mow, mob, uiw, uib, uow);
    }

    for (int l = 0; l < NL; l++) {
        // [a|bb] = h @ [W1a|W1b] + [b1|0]   (8192 x 256)
        gemm_tc<<<dim3(128, 2), 128, SMEM_TC>>>(
            ph, pB1h + l*4*8192, pB1l + l*4*8192,
            pbbias + l*2*HD, pab, 2*HD);
        // s_i = sum_k silu(a_i + bb_j + d*w1c)
        edge_k<<<NODES, 128>>>(miw, l);
        // h += silu(h@W3a + s@w2p + b2p) @ W4 + b4   (fused gemm2+3)
        gemm23_k<<<dim3(128, 1), 128, SMEM_TC>>>(
            ph, ps,
            pB2ah + l*2*8192, pB2al + l*2*8192,
            pB2bh + l*2*8192, pB2bl + l*2*8192,
            pB3h + l*2*8192,  pB3l + l*2*8192,
            pb2p + l*HD, uob + l*HD, ph);
    }
    out_k<<<(NODES*OUTD + 255)/256, 256>>>(ow, ob, out);
}

// round 16
// speedup vs baseline: 2.5359x; 1.2212x over previous
#include <cuda_runtime.h>
#include <cuda_bf16.h>
#include <cstdint>

// Problem constants
#define BT     4
#define NP     2048
#define NODES  (BT*NP)        // 8192
#define HD     128
#define KN     32
#define NL     4
#define OUTD   6

// ---------------- scratch (device globals; no allocation allowed) ----------
__device__ float g_h    [NODES*HD];
__device__ float g_ab   [NODES*2*HD];
__device__ float g_s    [NODES*HD];
__device__ int   g_idx  [NODES*KN];
__device__ float g_dn   [NODES*KN];
__device__ float g_bbias[NL*2*HD];         // [b1 | 0]
__device__ float g_w2p  [NL*HD*HD];        // W2 @ W3b (fp32)
__device__ float g_b2p  [NL*HD];           // K*b2 @ W3b + b3

// bf16 hi/lo chunk-swizzled B-tile images (one image = 64n x 128k = 8192 bf16 = 16KB)
__device__ __align__(16) __nv_bfloat16 g_B1h [NL*4*8192], g_B1l [NL*4*8192];   // [W1a|W1b]
__device__ __align__(16) __nv_bfloat16 g_B2ah[NL*2*8192], g_B2al[NL*2*8192];   // W3a
__device__ __align__(16) __nv_bfloat16 g_B2bh[NL*2*8192], g_B2bl[NL*2*8192];   // W2@W3b
__device__ __align__(16) __nv_bfloat16 g_B3h [NL*2*8192], g_B3l [NL*2*8192];   // W4

__device__ __forceinline__ float tanh_ap(float x) {
    float r; asm("tanh.approx.f32 %0, %1;" : "=f"(r) : "f"(x)); return r;
}
__device__ __forceinline__ float silu_f(float x) {
    float hx = 0.5f * x;
    return fmaf(hx, tanh_ap(hx), hx);
}
__device__ __forceinline__ uint32_t smem_u32(const void* p) {
    uint32_t a;
    asm("{ .reg .u64 t; cvta.to.shared.u64 t, %1; cvt.u32.u64 %0, t; }"
        : "=r"(a) : "l"(p));
    return a;
}
__device__ __forceinline__ uint32_t pack_bf2(__nv_bfloat16 lo, __nv_bfloat16 hi) {
    return (uint32_t)__bfloat16_as_ushort(lo) | ((uint32_t)__bfloat16_as_ushort(hi) << 16);
}
// byte offset of element (row r, bf16 col k) in a 64-row x 128-col tile,
// 256B/row, 16B chunks XOR-swizzled: chunk' = chunk ^ (r & 7)
__device__ __forceinline__ uint32_t tile_off(int r, int k) {
    uint32_t ch = (uint32_t)(k >> 3);
    return (uint32_t)r*256u + ((ch ^ (uint32_t)(r & 7)) << 4) + (uint32_t)(k & 7)*2u;
}
// pack fp32 pair -> hi/lo u32s
__device__ __forceinline__ void split2(float v0, float v1, uint32_t& hw, uint32_t& lw) {
    __nv_bfloat16 h0 = __float2bfloat16(v0), h1 = __float2bfloat16(v1);
    hw = pack_bf2(h0, h1);
    lw = pack_bf2(__float2bfloat16(v0 - __bfloat162float(h0)),
                  __float2bfloat16(v1 - __bfloat162float(h1)));
}

__device__ __forceinline__ void ldm4(uint32_t& r0, uint32_t& r1,
                                     uint32_t& r2, uint32_t& r3, uint32_t addr) {
    asm volatile("ldmatrix.sync.aligned.m8n8.x4.shared.b16 {%0,%1,%2,%3}, [%4];"
                 : "=r"(r0), "=r"(r1), "=r"(r2), "=r"(r3) : "r"(addr));
}
__device__ __forceinline__ void mma16816(float* c, uint32_t a0, uint32_t a1,
                                         uint32_t a2, uint32_t a3,
                                         uint32_t b0, uint32_t b1) {
    asm volatile(
        "mma.sync.aligned.m16n8k16.row.col.f32.bf16.bf16.f32 "
        "{%0,%1,%2,%3}, {%4,%5,%6,%7}, {%8,%9}, {%0,%1,%2,%3};"
        : "+f"(c[0]), "+f"(c[1]), "+f"(c[2]), "+f"(c[3])
        : "r"(a0), "r"(a1), "r"(a2), "r"(a3), "r"(b0), "r"(b1));
}

// smem layout for the HMMA kernels
#define SM_AH  0
#define SM_AL  16384
#define SM_BH0 32768
#define SM_BL0 49152
#define SM_BH1 65536
#define SM_BL1 81920
#define SMEM_TC 98304

// ---------------- embed ----------------------------------------------------
__global__ void embed_k(const float* __restrict__ x,
                        const float* __restrict__ ew,
                        const float* __restrict__ eb) {
    int t = blockIdx.x * blockDim.x + threadIdx.x;
    int node = t >> 7, c = t & 127;
    float acc = eb[c];
    acc += x[node*3+0] * ew[c];
    acc += x[node*3+1] * ew[HD + c];
    acc += x[node*3+2] * ew[2*HD + c];
    g_h[t] = acc;
}

// ---------------- KNN (known-good) ------------------------------------------
#define TOP4_INS(v, jj)                                                  \
    if ((v) < m4) {                                                      \
        if ((v) < m1)      { m4=m3;j4=j3; m3=m2;j3=j2; m2=m1;j2=j1; m1=(v);j1=(jj); } \
        else if ((v) < m2) { m4=m3;j4=j3; m3=m2;j3=j2; m2=(v);j2=(jj); } \
        else if ((v) < m3) { m4=m3;j4=j3; m3=(v);j3=(jj); }              \
        else               { m4=(v);j4=(jj); }                           \
    }

__global__ void __launch_bounds__(128) knn_k(const float* __restrict__ x) {
    __shared__ float sd[4][NP];
    const float FINF = __int_as_float(0x7f800000);
    int w = threadIdx.x >> 5, lane = threadIdx.x & 31;
    int node = blockIdx.x * 4 + w;
    int b = node >> 11;
    int i = node & (NP - 1);
    const float* xb = x + b * NP * 3;
    float xi0 = x[node*3+0], xi1 = x[node*3+1], xi2 = x[node*3+2];
    float* dist = sd[w];

    for (int jj = lane; jj < NP; jj += 32) {
        float dx = __fadd_rn(xi0, -xb[jj*3+0]);
        float dy = __fadd_rn(xi1, -xb[jj*3+1]);
        float dz = __fadd_rn(xi2, -xb[jj*3+2]);
        float dq = __fadd_rn(__fadd_rn(__fmul_rn(dx,dx), __fmul_rn(dy,dy)),
                             __fmul_rn(dz,dz));
        dist[jj] = (jj == i) ? FINF : dq;
    }
    __syncwarp();

    float m1=FINF, m2=FINF, m3=FINF, m4=FINF;
    int   j1=lane, j2=lane, j3=lane, j4=lane;
    #pragma unroll
    for (int tt = 0; tt < NP/32; tt++) {
        int jj = lane + (tt << 5);
        float v = dist[jj];
        TOP4_INS(v, jj);
    }

    for (int r = 0; r < KN; r++) {
        float bv = m1; int bj = j1;
        #pragma unroll
        for (int off = 16; off; off >>= 1) {
            float ov = __shfl_down_sync(0xffffffffu, bv, off);
            int   oj = __shfl_down_sync(0xffffffffu, bj, off);
            if (ov < bv) { bv = ov; bj = oj; }
        }
        bv = __shfl_sync(0xffffffffu, bv, 0);
        bj = __shfl_sync(0xffffffffu, bj, 0);
        if (lane == 0) {
            g_idx[node*KN + r] = b * NP + bj;
            g_dn [node*KN + r] = sqrtf(bv);
        }
        if ((bj & 31) == lane) {
            dist[bj] = FINF;
            m1=m2; j1=j2; m2=m3; j2=j3; m3=m4; j3=j4; m4=FINF; j4=lane;
            if (!(m1 < FINF)) {
                m1=m2=m3=m4=FINF; j1=j2=j3=j4=lane;
                #pragma unroll
                for (int tt = 0; tt < NP/32; tt++) {
                    int jj = lane + (tt << 5);
                    float v = dist[jj];
                    TOP4_INS(v, jj);
                }
            }
        }
    }
}

// ---------------- prep1: fp32 folded weights / biases (coalesced w2p) -------
__global__ void prep_k(const float* __restrict__ mib,
                       const float* __restrict__ mow, const float* __restrict__ mob,
                       const float* __restrict__ uiw, const float* __restrict__ uib) {
    int t = blockIdx.x * blockDim.x + threadIdx.x;
    if (t < NL*2*HD) {
        int l = t / (2*HD); int j = t % (2*HD);
        g_bbias[t] = (j < HD) ? mib[l*HD + j] : 0.0f;
        return;
    }
    int u = t - NL*2*HD;
    if (u < NL*HD*HD) {
        int l = u / (HD*HD); int rem = u % (HD*HD);
        int r = rem / HD; int c = rem % HD;           // consecutive threads: consecutive c
        const float* W2  = mow + l*HD*HD;
        const float* W3b = uiw + l*2*HD*HD + HD*HD;
        float acc = 0.0f;
        for (int k = 0; k < HD; k++) acc += W2[r*HD + k] * W3b[k*HD + c];
        g_w2p[u] = acc;
        return;
    }
    u -= NL*HD*HD;
    if (u < NL*HD) {
        int l = u / HD; int c = u % HD;
        const float* b2  = mob + l*HD;
        const float* W3b = uiw + l*2*HD*HD + HD*HD;
        float acc = uib[l*HD + c];
        for (int k = 0; k < HD; k++) acc += (float)KN * b2[k] * W3b[k*HD + c];
        g_b2p[u] = acc;
        return;
    }
}

// ---------------- prep2: bf16 hi/lo chunk-swizzled B-tile images ------------
__global__ void prep2_k(const float* __restrict__ miw,
                        const float* __restrict__ uiw,
                        const float* __restrict__ uow) {
    const int PER_L = 10*8192;
    int t = blockIdx.x * blockDim.x + threadIdx.x;
    if (t >= NL*PER_L) return;
    int l = t / PER_L, u = t % PER_L;
    int region = u / 8192;            // 0..9
    int e = u & 8191;
    int tile, n_local = e >> 7, k = e & 127;
    float src;
    __nv_bfloat16 *dh, *dl;
    if (region < 4) {                 // gemm1 B: [W1a|W1b] col n, row k of W1
        tile = region;
        int n = tile*64 + n_local;
        const float* W1 = miw + l*257*HD;
        src = (n < HD) ? W1[k*HD + n] : W1[(HD + k)*HD + (n - HD)];
        dh = g_B1h + (l*4 + tile)*8192; dl = g_B1l + (l*4 + tile)*8192;
    } else if (region < 6) {          // W3a
        tile = region - 4;
        int n = tile*64 + n_local;
        src = uiw[l*2*HD*HD + k*HD + n];
        dh = g_B2ah + (l*2 + tile)*8192; dl = g_B2al + (l*2 + tile)*8192;
    } else if (region < 8) {          // w2p (fp32, from prep_k)
        tile = region - 6;
        int n = tile*64 + n_local;
        src = g_w2p[l*HD*HD + k*HD + n];
        dh = g_B2bh + (l*2 + tile)*8192; dl = g_B2bl + (l*2 + tile)*8192;
    } else {                          // W4
        tile = region - 8;
        int n = tile*64 + n_local;
        src = uow[l*HD*HD + k*HD + n];
        dh = g_B3h + (l*2 + tile)*8192; dl = g_B3l + (l*2 + tile)*8192;
    }
    __nv_bfloat16 hi = __float2bfloat16(src);
    __nv_bfloat16 lo = __float2bfloat16(src - __bfloat162float(hi));
    uint32_t eoff = tile_off(n_local, k) >> 1;
    dh[eoff] = hi; dl[eoff] = lo;
}

// ---------------- edge pass (standalone, 8192 blocks) -----------------------
__global__ void __launch_bounds__(128) edge_k(const float* __restrict__ miw, int l) {
    int node = blockIdx.x;
    int c = threadIdx.x;
    __shared__ int   sj[KN];
    __shared__ float sdd[KN];
    if (c < KN) {
        sj[c]  = g_idx[node*KN + c];
        sdd[c] = g_dn [node*KN + c];
    }
    __syncthreads();
    float ai = g_ab[node*2*HD + c];
    float wc = miw[l*257*HD + 256*HD + c];
    float acc = 0.0f;
    #pragma unroll 8
    for (int k = 0; k < KN; k++) {
        int j = sj[k];
        float v = ai + g_ab[j*2*HD + HD + c] + sdd[k] * wc;
        acc += silu_f(v);
    }
    g_s[node*HD + c] = acc;
}

// ======== shared device helpers for the HMMA kernels (128 threads) ==========
__device__ __forceinline__ void stage_A(char* smem, const float* __restrict__ A,
                                        int rowBase, int tid) {
    #pragma unroll
    for (int i = 0; i < 8; i++) {
        int id = tid + 128*i;               // 1024 chunks
        int r = id >> 4, ch = id & 15;
        const float* src = A + (size_t)(rowBase + r)*HD + ch*8;
        float4 a0 = *(const float4*)(src);
        float4 a1 = *(const float4*)(src + 4);
        uint4 hv, lv;
        split2(a0.x, a0.y, hv.x, lv.x);
        split2(a0.z, a0.w, hv.y, lv.y);
        split2(a1.x, a1.y, hv.z, lv.z);
        split2(a1.z, a1.w, hv.w, lv.w);
        uint32_t off = (uint32_t)r*256u + (((uint32_t)ch ^ (uint32_t)(r & 7)) << 4);
        *(uint4*)(smem + SM_AH + off) = hv;
        *(uint4*)(smem + SM_AL + off) = lv;
    }
}
__device__ __forceinline__ void stage_B(char* smem,
                                        const __nv_bfloat16* __restrict__ Bh,
                                        const __nv_bfloat16* __restrict__ Bl,
                                        int tid) {
    #pragma unroll
    for (int i = 0; i < 8; i++) {
        int id = tid + 128*i;
        *(uint4*)(smem + SM_BH0 + id*16) = ((const uint4*)Bh)[id];
        *(uint4*)(smem + SM_BH1 + id*16) = ((const uint4*)(Bh + 8192))[id];
        *(uint4*)(smem + SM_BL0 + id*16) = ((const uint4*)Bl)[id];
        *(uint4*)(smem + SM_BL1 + id*16) = ((const uint4*)(Bl + 8192))[id];
    }
}
// one full K=128 MMA pass (3-term split), accumulating into acc[2][8][4]
__device__ __forceinline__ void mma_pass(uint32_t sb, float acc[2][8][4],
                                         uint32_t aBase0, uint32_t aBase1,
                                         uint32_t sBH, uint32_t sBL,
                                         uint32_t sw, int lrow, int lkoff) {
    #pragma unroll
    for (int ks = 0; ks < 8; ks++) {
        uint32_t kc = (uint32_t)(ks*2 + lkoff);
        uint32_t koff = ((kc ^ sw) << 4);
        uint32_t ah[8], al[8];
        ldm4(ah[0], ah[1], ah[2], ah[3], sb + SM_AH + aBase0 + koff);
        ldm4(ah[4], ah[5], ah[6], ah[7], sb + SM_AH + aBase1 + koff);
        ldm4(al[0], al[1], al[2], al[3], sb + SM_AL + aBase0 + koff);
        ldm4(al[4], al[5], al[6], al[7], sb + SM_AL + aBase1 + koff);
        #pragma unroll
        for (int q = 0; q < 4; q++) {
            uint32_t bh[4], bl[4];
            uint32_t bBase = (uint32_t)(q*16 + lrow)*256u + koff;
            ldm4(bh[0], bh[1], bh[2], bh[3], sBH + bBase);
            ldm4(bl[0], bl[1], bl[2], bl[3], sBL + bBase);
            #pragma unroll
            for (int mi = 0; mi < 2; mi++) {
                uint32_t* a = ah + mi*4;
                uint32_t* c = al + mi*4;
                mma16816(acc[mi][2*q+0], a[0], a[1], a[2], a[3], bh[0], bh[2]);
                mma16816(acc[mi][2*q+1], a[0], a[1], a[2], a[3], bh[1], bh[3]);
                mma16816(acc[mi][2*q+0], a[0], a[1], a[2], a[3], bl[0], bl[2]);
                mma16816(acc[mi][2*q+1], a[0], a[1], a[2], a[3], bl[1], bl[3]);
                mma16816(acc[mi][2*q+0], c[0], c[1], c[2], c[3], bh[0], bh[2]);
                mma16816(acc[mi][2*q+1], c[0], c[1], c[2], c[3], bh[1], bh[3]);
            }
        }
    }
}

// ---------------- gemm1: ab = h @ [W1a|W1b] + [b1|0]  (BN=128, 4 warps) -----
__global__ void __launch_bounds__(128) gemm_tc(
    const float* __restrict__ A0,
    const __nv_bfloat16* __restrict__ B0h, const __nv_bfloat16* __restrict__ B0l,
    const float* __restrict__ bias,
    float* __restrict__ C, int N)
{
    extern __shared__ char smem[];
    uint32_t sb = smem_u32(smem);
    const int tid  = threadIdx.x;
    const int wid  = tid >> 5, lane = tid & 31;
    const int rowBase = blockIdx.x * 64;
    const int colBase = blockIdx.y * 128;
    const int wm = (wid & 1) * 32, wn = (wid >> 1) * 64;

    float acc[2][8][4];
    #pragma unroll
    for (int mi = 0; mi < 2; mi++)
        #pragma unroll
        for (int ni = 0; ni < 8; ni++)
            #pragma unroll
            for (int q = 0; q < 4; q++) acc[mi][ni][q] = 0.0f;

    const int lrow  = lane & 15;
    const int lkoff = lane >> 4;
    const uint32_t sw = (uint32_t)(lrow & 7);
    const uint32_t aBase0 = (uint32_t)(wm + lrow)*256u;
    const uint32_t aBase1 = (uint32_t)(wm + 16 + lrow)*256u;
    const uint32_t sBH = sb + (wn ? SM_BH1 : SM_BH0);
    const uint32_t sBL = sb + (wn ? SM_BL1 : SM_BL0);

    stage_A(smem, A0, rowBase, tid);
    stage_B(smem, B0h + (blockIdx.y*2)*8192, B0l + (blockIdx.y*2)*8192, tid);
    __syncthreads();
    mma_pass(sb, acc, aBase0, aBase1, sBH, sBL, sw, lrow, lkoff);

    const int erow = lane >> 2;
    const int ecol = (lane & 3) * 2;
    #pragma unroll
    for (int mi = 0; mi < 2; mi++) {
        #pragma unroll
        for (int ni = 0; ni < 8; ni++) {
            int row = rowBase + wm + mi*16 + erow;
            int col = colBase + wn + ni*8 + ecol;
            float bx = bias[col], by = bias[col+1];
            *(float2*)(C + (size_t)row*N + col) =
                make_float2(acc[mi][ni][0] + bx, acc[mi][ni][1] + by);
            *(float2*)(C + (size_t)(row+8)*N + col) =
                make_float2(acc[mi][ni][2] + bx, acc[mi][ni][3] + by);
        }
    }
}

// ---------------- gemm23: h += silu(h@W3a + s@w2p + b2p) @ W4 + b4 ----------
// grid (128): CTA owns 64 rows, full 128-col width, 4 warps.
__global__ void __launch_bounds__(128) gemm23_k(
    const float* __restrict__ Ah_, const float* __restrict__ As_,
    const __nv_bfloat16* __restrict__ B2ah, const __nv_bfloat16* __restrict__ B2al,
    const __nv_bfloat16* __restrict__ B2bh, const __nv_bfloat16* __restrict__ B2bl,
    const __nv_bfloat16* __restrict__ B3h,  const __nv_bfloat16* __restrict__ B3l,
    const float* __restrict__ b2p, const float* __restrict__ b4,
    float* __restrict__ H)
{
    extern __shared__ char smem[];
    uint32_t sb = smem_u32(smem);
    const int tid  = threadIdx.x;
    const int wid  = tid >> 5, lane = tid & 31;
    const int rowBase = blockIdx.x * 64;
    const int wm = (wid & 1) * 32, wn = (wid >> 1) * 64;

    float acc[2][8][4];
    #pragma unroll
    for (int mi = 0; mi < 2; mi++)
        #pragma unroll
        for (int ni = 0; ni < 8; ni++)
            #pragma unroll
            for (int q = 0; q < 4; q++) acc[mi][ni][q] = 0.0f;

    const int lrow  = lane & 15;
    const int lkoff = lane >> 4;
    const uint32_t sw = (uint32_t)(lrow & 7);
    const uint32_t aBase0 = (uint32_t)(wm + lrow)*256u;
    const uint32_t aBase1 = (uint32_t)(wm + 16 + lrow)*256u;
    const uint32_t sBH = sb + (wn ? SM_BH1 : SM_BH0);
    const uint32_t sBL = sb + (wn ? SM_BL1 : SM_BL0);
    const int erow = lane >> 2;
    const int ecol = (lane & 3) * 2;

    // ---- pass 1: h @ W3a ----
    stage_A(smem, Ah_, rowBase, tid);
    stage_B(smem, B2ah, B2al, tid);
    __syncthreads();
    mma_pass(sb, acc, aBase0, aBase1, sBH, sBL, sw, lrow, lkoff);

    // ---- pass 2: + s @ w2p ----
    __syncthreads();
    stage_A(smem, As_, rowBase, tid);
    stage_B(smem, B2bh, B2bl, tid);
    __syncthreads();
    mma_pass(sb, acc, aBase0, aBase1, sBH, sBL, sw, lrow, lkoff);

    // ---- mid epilogue: p2 = silu(acc + b2p) -> smem A (swizzled hi/lo) ----
    __syncthreads();                  // all warps done reading SM_AH/AL
    #pragma unroll
    for (int mi = 0; mi < 2; mi++) {
        #pragma unroll
        for (int ni = 0; ni < 8; ni++) {
            int rl0 = wm + mi*16 + erow;
            int col = wn + ni*8 + ecol;
            float bx = b2p[col], by = b2p[col+1];
            float v00 = silu_f(acc[mi][ni][0] + bx);
            float v01 = silu_f(acc[mi][ni][1] + by);
            float v10 = silu_f(acc[mi][ni][2] + bx);
            float v11 = silu_f(acc[mi][ni][3] + by);
            uint32_t hw, lw;
            split2(v00, v01, hw, lw);
            uint32_t o = tile_off(rl0, col);
            *(uint32_t*)(smem + SM_AH + o) = hw;
            *(uint32_t*)(smem + SM_AL + o) = lw;
            split2(v10, v11, hw, lw);
            o = tile_off(rl0 + 8, col);
            *(uint32_t*)(smem + SM_AH + o) = hw;
            *(uint32_t*)(smem + SM_AL + o) = lw;
            acc[mi][ni][0] = acc[mi][ni][1] = acc[mi][ni][2] = acc[mi][ni][3] = 0.0f;
        }
    }
    // ---- pass 3: p2 @ W4 ----
    stage_B(smem, B3h, B3l, tid);
    __syncthreads();                  // orders p2 writes + B3 staging before reads
    mma_pass(sb, acc, aBase0, aBase1, sBH, sBL, sw, lrow, lkoff);

    // ---- final epilogue: h += . + b4 ----
    #pragma unroll
    for (int mi = 0; mi < 2; mi++) {
        #pragma unroll
        for (int ni = 0; ni < 8; ni++) {
            int row = rowBase + wm + mi*16 + erow;
            int col = wn + ni*8 + ecol;
            float bx = b4[col], by = b4[col+1];
            float* h0 = H + (size_t)row*HD + col;
            float* h1 = H + (size_t)(row+8)*HD + col;
            float2 e0 = *(float2*)h0;
            float2 e1 = *(float2*)h1;
            *(float2*)h0 = make_float2(acc[mi][ni][0] + bx + e0.x,
                                       acc[mi][ni][1] + by + e0.y);
            *(float2*)h1 = make_float2(acc[mi][ni][2] + bx + e1.x,
                                       acc[mi][ni][3] + by + e1.y);
        }
    }
}

// ---------------- final projection ------------------------------------------
__global__ void out_k(const float* __restrict__ ow, const float* __restrict__ ob,
                      float* __restrict__ out) {
    int t = blockIdx.x * blockDim.x + threadIdx.x;
    if (t >= NODES*OUTD) return;
    int node = t / OUTD, oc = t % OUTD;
    float acc = ob[oc];
    #pragma unroll 8
    for (int k = 0; k < HD; k++) acc += g_h[node*HD + k] * ow[k*OUTD + oc];
    out[t] = acc;
}

// ---------------------------------------------------------------------------
extern "C" void kernel_launch(void* const* d_in, const int* in_sizes, int n_in,
                              void* d_out, int out_size) {
    const float* x   = (const float*)d_in[0];
    const float* ew  = (const float*)d_in[1];
    const float* eb  = (const float*)d_in[2];
    const float* miw = (const float*)d_in[3];
    const float* mib = (const float*)d_in[4];
    const float* mow = (const float*)d_in[5];
    const float* mob = (const float*)d_in[6];
    const float* uiw = (const float*)d_in[7];
    const float* uib = (const float*)d_in[8];
    const float* uow = (const float*)d_in[9];
    const float* uob = (const float*)d_in[10];
    const float* ow  = (const float*)d_in[11];
    const float* ob  = (const float*)d_in[12];
    float* out = (float*)d_out;

    cudaFuncSetAttribute(gemm_tc,  cudaFuncAttributeMaxDynamicSharedMemorySize, SMEM_TC);
    cudaFuncSetAttribute(gemm23_k, cudaFuncAttributeMaxDynamicSharedMemorySize, SMEM_TC);

    float *ph, *pab, *ps, *pbbias, *pb2p;
    __nv_bfloat16 *pB1h, *pB1l, *pB2ah, *pB2al, *pB2bh, *pB2bl, *pB3h, *pB3l;
    cudaGetSymbolAddress((void**)&ph,     g_h);
    cudaGetSymbolAddress((void**)&pab,    g_ab);
    cudaGetSymbolAddress((void**)&ps,     g_s);
    cudaGetSymbolAddress((void**)&pbbias, g_bbias);
    cudaGetSymbolAddress((void**)&pb2p,   g_b2p);
    cudaGetSymbolAddress((void**)&pB1h,   g_B1h);
    cudaGetSymbolAddress((void**)&pB1l,   g_B1l);
    cudaGetSymbolAddress((void**)&pB2ah,  g_B2ah);
    cudaGetSymbolAddress((void**)&pB2al,  g_B2al);
    cudaGetSymbolAddress((void**)&pB2bh,  g_B2bh);
    cudaGetSymbolAddress((void**)&pB2bl,  g_B2bl);
    cudaGetSymbolAddress((void**)&pB3h,   g_B3h);
    cudaGetSymbolAddress((void**)&pB3l,   g_B3l);

    embed_k<<<NODES*HD/256, 256>>>(x, ew, eb);
    knn_k<<<NODES/4, 128>>>(x);
    {
        int total = NL*2*HD + NL*HD*HD + NL*HD;
        prep_k<<<(total + 255)/256, 256>>>(mib, mow, mob, uiw, uib);
        prep2_k<<<(NL*10*8192 + 255)/256, 256>>>(miw, uiw, uow);
    }

    for (int l = 0; l < NL; l++) {
        // [a|bb] = h @ [W1a|W1b] + [b1|0]   (8192 x 256)
        gemm_tc<<<dim3(128, 2), 128, SMEM_TC>>>(
            ph, pB1h + l*4*8192, pB1l + l*4*8192,
            pbbias + l*2*HD, pab, 2*HD);
        // s_i = sum_k silu(a_i + bb_j + d*w1c)
        edge_k<<<NODES, 128>>>(miw, l);
        // h += silu(h@W3a + s@w2p + b2p) @ W4 + b4   (fused gemm2+3)
        gemm23_k<<<dim3(128, 1), 128, SMEM_TC>>>(
            ph, ps,
            pB2ah + l*2*8192, pB2al + l*2*8192,
            pB2bh + l*2*8192, pB2bl + l*2*8192,
            pB3h + l*2*8192,  pB3l + l*2*8192,
            pb2p + l*HD, uob + l*HD, ph);
    }
    out_k<<<(NODES*OUTD + 255)/256, 256>>>(ow, ob, out);
}

// round 17
// speedup vs baseline: 2.5501x; 1.0056x over previous
#include <cuda_runtime.h>
#include <cuda_bf16.h>
#include <cstdint>

// Problem constants
#define BT     4
#define NP     2048
#define NODES  (BT*NP)        // 8192
#define HD     128
#define KN     32
#define NL     4
#define OUTD   6

// ---------------- scratch (device globals; no allocation allowed) ----------
__device__ float g_h    [NODES*HD];
__device__ float g_ab   [NODES*2*HD];
__device__ float g_s    [NODES*HD];
__device__ int   g_idx  [NODES*KN];
__device__ float g_dn   [NODES*KN];
__device__ float g_bbias[NL*2*HD];         // [b1 | 0]
__device__ float g_w2p  [NL*HD*HD];        // W2 @ W3b (fp32)
__device__ float g_b2p  [NL*HD];           // K*b2 @ W3b + b3

// bf16 hi/lo chunk-swizzled B-tile images (one image = 64n x 128k = 8192 bf16 = 16KB)
__device__ __align__(16) __nv_bfloat16 g_B1h [NL*4*8192], g_B1l [NL*4*8192];   // [W1a|W1b]
__device__ __align__(16) __nv_bfloat16 g_B2ah[NL*2*8192], g_B2al[NL*2*8192];   // W3a
__device__ __align__(16) __nv_bfloat16 g_B2bh[NL*2*8192], g_B2bl[NL*2*8192];   // W2@W3b
__device__ __align__(16) __nv_bfloat16 g_B3h [NL*2*8192], g_B3l [NL*2*8192];   // W4

__device__ __forceinline__ float tanh_ap(float x) {
    float r; asm("tanh.approx.f32 %0, %1;" : "=f"(r) : "f"(x)); return r;
}
__device__ __forceinline__ float silu_f(float x) {
    float hx = 0.5f * x;
    return fmaf(hx, tanh_ap(hx), hx);
}
__device__ __forceinline__ uint32_t smem_u32(const void* p) {
    uint32_t a;
    asm("{ .reg .u64 t; cvta.to.shared.u64 t, %1; cvt.u32.u64 %0, t; }"
        : "=r"(a) : "l"(p));
    return a;
}
__device__ __forceinline__ uint32_t pack_bf2(__nv_bfloat16 lo, __nv_bfloat16 hi) {
    return (uint32_t)__bfloat16_as_ushort(lo) | ((uint32_t)__bfloat16_as_ushort(hi) << 16);
}
// byte offset of element (row r, bf16 col k) in a 64-row x 128-col tile,
// 256B/row, 16B chunks XOR-swizzled: chunk' = chunk ^ (r & 7)
__device__ __forceinline__ uint32_t tile_off(int r, int k) {
    uint32_t ch = (uint32_t)(k >> 3);
    return (uint32_t)r*256u + ((ch ^ (uint32_t)(r & 7)) << 4) + (uint32_t)(k & 7)*2u;
}
// pack fp32 pair -> hi/lo u32s
__device__ __forceinline__ void split2(float v0, float v1, uint32_t& hw, uint32_t& lw) {
    __nv_bfloat16 h0 = __float2bfloat16(v0), h1 = __float2bfloat16(v1);
    hw = pack_bf2(h0, h1);
    lw = pack_bf2(__float2bfloat16(v0 - __bfloat162float(h0)),
                  __float2bfloat16(v1 - __bfloat162float(h1)));
}

__device__ __forceinline__ void ldm4(uint32_t& r0, uint32_t& r1,
                                     uint32_t& r2, uint32_t& r3, uint32_t addr) {
    asm volatile("ldmatrix.sync.aligned.m8n8.x4.shared.b16 {%0,%1,%2,%3}, [%4];"
                 : "=r"(r0), "=r"(r1), "=r"(r2), "=r"(r3) : "r"(addr));
}
__device__ __forceinline__ void mma16816(float* c, uint32_t a0, uint32_t a1,
                                         uint32_t a2, uint32_t a3,
                                         uint32_t b0, uint32_t b1) {
    asm volatile(
        "mma.sync.aligned.m16n8k16.row.col.f32.bf16.bf16.f32 "
        "{%0,%1,%2,%3}, {%4,%5,%6,%7}, {%8,%9}, {%0,%1,%2,%3};"
        : "+f"(c[0]), "+f"(c[1]), "+f"(c[2]), "+f"(c[3])
        : "r"(a0), "r"(a1), "r"(a2), "r"(a3), "r"(b0), "r"(b1));
}
// cp.async helpers (sm_80 baseline PTX)
__device__ __forceinline__ void cpa16(uint32_t saddr, const void* g) {
    asm volatile("cp.async.cg.shared.global [%0], [%1], 16;" :: "r"(saddr), "l"(g));
}
#define CP_COMMIT() asm volatile("cp.async.commit_group;" ::: "memory")
#define CP_WAIT(n)  asm volatile("cp.async.wait_group %0;" :: "n"(n) : "memory")

// smem maps
// gemm_tc:  A @0 (AH 16K + AL 16K), Bset @32768 (BH0,BL0,BH1,BL1) -> 96KB
// gemm23_k: A @0, B0 @32768, B1 @98304, SRAW @163840             -> 224KB
#define A_OFF    0
#define B0_OFF   32768
#define B1_OFF   98304
#define SRAW_OFF 163840
#define SMEM_G1  98304
#define SMEM_G23 229376

// ---------------- embed ----------------------------------------------------
__global__ void embed_k(const float* __restrict__ x,
                        const float* __restrict__ ew,
                        const float* __restrict__ eb) {
    int t = blockIdx.x * blockDim.x + threadIdx.x;
    int node = t >> 7, c = t & 127;
    float acc = eb[c];
    acc += x[node*3+0] * ew[c];
    acc += x[node*3+1] * ew[HD + c];
    acc += x[node*3+2] * ew[2*HD + c];
    g_h[t] = acc;
}

// ---------------- KNN (known-good) ------------------------------------------
#define TOP4_INS(v, jj)                                                  \
    if ((v) < m4) {                                                      \
        if ((v) < m1)      { m4=m3;j4=j3; m3=m2;j3=j2; m2=m1;j2=j1; m1=(v);j1=(jj); } \
        else if ((v) < m2) { m4=m3;j4=j3; m3=m2;j3=j2; m2=(v);j2=(jj); } \
        else if ((v) < m3) { m4=m3;j4=j3; m3=(v);j3=(jj); }              \
        else               { m4=(v);j4=(jj); }                           \
    }

__global__ void __launch_bounds__(128) knn_k(const float* __restrict__ x) {
    __shared__ float sd[4][NP];
    const float FINF = __int_as_float(0x7f800000);
    int w = threadIdx.x >> 5, lane = threadIdx.x & 31;
    int node = blockIdx.x * 4 + w;
    int b = node >> 11;
    int i = node & (NP - 1);
    const float* xb = x + b * NP * 3;
    float xi0 = x[node*3+0], xi1 = x[node*3+1], xi2 = x[node*3+2];
    float* dist = sd[w];

    for (int jj = lane; jj < NP; jj += 32) {
        float dx = __fadd_rn(xi0, -xb[jj*3+0]);
        float dy = __fadd_rn(xi1, -xb[jj*3+1]);
        float dz = __fadd_rn(xi2, -xb[jj*3+2]);
        float dq = __fadd_rn(__fadd_rn(__fmul_rn(dx,dx), __fmul_rn(dy,dy)),
                             __fmul_rn(dz,dz));
        dist[jj] = (jj == i) ? FINF : dq;
    }
    __syncwarp();

    float m1=FINF, m2=FINF, m3=FINF, m4=FINF;
    int   j1=lane, j2=lane, j3=lane, j4=lane;
    #pragma unroll
    for (int tt = 0; tt < NP/32; tt++) {
        int jj = lane + (tt << 5);
        float v = dist[jj];
        TOP4_INS(v, jj);
    }

    for (int r = 0; r < KN; r++) {
        float bv = m1; int bj = j1;
        #pragma unroll
        for (int off = 16; off; off >>= 1) {
            float ov = __shfl_down_sync(0xffffffffu, bv, off);
            int   oj = __shfl_down_sync(0xffffffffu, bj, off);
            if (ov < bv) { bv = ov; bj = oj; }
        }
        bv = __shfl_sync(0xffffffffu, bv, 0);
        bj = __shfl_sync(0xffffffffu, bj, 0);
        if (lane == 0) {
            g_idx[node*KN + r] = b * NP + bj;
            g_dn [node*KN + r] = sqrtf(bv);
        }
        if ((bj & 31) == lane) {
            dist[bj] = FINF;
            m1=m2; j1=j2; m2=m3; j2=j3; m3=m4; j3=j4; m4=FINF; j4=lane;
            if (!(m1 < FINF)) {
                m1=m2=m3=m4=FINF; j1=j2=j3=j4=lane;
                #pragma unroll
                for (int tt = 0; tt < NP/32; tt++) {
                    int jj = lane + (tt << 5);
                    float v = dist[jj];
                    TOP4_INS(v, jj);
                }
            }
        }
    }
}

// ---------------- prep1: fp32 folded weights / biases (coalesced w2p) -------
__global__ void prep_k(const float* __restrict__ mib,
                       const float* __restrict__ mow, const float* __restrict__ mob,
                       const float* __restrict__ uiw, const float* __restrict__ uib) {
    int t = blockIdx.x * blockDim.x + threadIdx.x;
    if (t < NL*2*HD) {
        int l = t / (2*HD); int j = t % (2*HD);
        g_bbias[t] = (j < HD) ? mib[l*HD + j] : 0.0f;
        return;
    }
    int u = t - NL*2*HD;
    if (u < NL*HD*HD) {
        int l = u / (HD*HD); int rem = u % (HD*HD);
        int r = rem / HD; int c = rem % HD;
        const float* W2  = mow + l*HD*HD;
        const float* W3b = uiw + l*2*HD*HD + HD*HD;
        float acc = 0.0f;
        for (int k = 0; k < HD; k++) acc += W2[r*HD + k] * W3b[k*HD + c];
        g_w2p[u] = acc;
        return;
    }
    u -= NL*HD*HD;
    if (u < NL*HD) {
        int l = u / HD; int c = u % HD;
        const float* b2  = mob + l*HD;
        const float* W3b = uiw + l*2*HD*HD + HD*HD;
        float acc = uib[l*HD + c];
        for (int k = 0; k < HD; k++) acc += (float)KN * b2[k] * W3b[k*HD + c];
        g_b2p[u] = acc;
        return;
    }
}

// ---------------- prep2: bf16 hi/lo chunk-swizzled B-tile images ------------
__global__ void prep2_k(const float* __restrict__ miw,
                        const float* __restrict__ uiw,
                        const float* __restrict__ uow) {
    const int PER_L = 10*8192;
    int t = blockIdx.x * blockDim.x + threadIdx.x;
    if (t >= NL*PER_L) return;
    int l = t / PER_L, u = t % PER_L;
    int region = u / 8192;            // 0..9
    int e = u & 8191;
    int tile, n_local = e >> 7, k = e & 127;
    float src;
    __nv_bfloat16 *dh, *dl;
    if (region < 4) {
        tile = region;
        int n = tile*64 + n_local;
        const float* W1 = miw + l*257*HD;
        src = (n < HD) ? W1[k*HD + n] : W1[(HD + k)*HD + (n - HD)];
        dh = g_B1h + (l*4 + tile)*8192; dl = g_B1l + (l*4 + tile)*8192;
    } else if (region < 6) {
        tile = region - 4;
        int n = tile*64 + n_local;
        src = uiw[l*2*HD*HD + k*HD + n];
        dh = g_B2ah + (l*2 + tile)*8192; dl = g_B2al + (l*2 + tile)*8192;
    } else if (region < 8) {
        tile = region - 6;
        int n = tile*64 + n_local;
        src = g_w2p[l*HD*HD + k*HD + n];
        dh = g_B2bh + (l*2 + tile)*8192; dl = g_B2bl + (l*2 + tile)*8192;
    } else {
        tile = region - 8;
        int n = tile*64 + n_local;
        src = uow[l*HD*HD + k*HD + n];
        dh = g_B3h + (l*2 + tile)*8192; dl = g_B3l + (l*2 + tile)*8192;
    }
    __nv_bfloat16 hi = __float2bfloat16(src);
    __nv_bfloat16 lo = __float2bfloat16(src - __bfloat162float(hi));
    uint32_t eoff = tile_off(n_local, k) >> 1;
    dh[eoff] = hi; dl[eoff] = lo;
}

// ---------------- edge pass (standalone, 8192 blocks) -----------------------
__global__ void __launch_bounds__(128) edge_k(const float* __restrict__ miw, int l) {
    int node = blockIdx.x;
    int c = threadIdx.x;
    __shared__ int   sj[KN];
    __shared__ float sdd[KN];
    if (c < KN) {
        sj[c]  = g_idx[node*KN + c];
        sdd[c] = g_dn [node*KN + c];
    }
    __syncthreads();
    float ai = g_ab[node*2*HD + c];
    float wc = miw[l*257*HD + 256*HD + c];
    float acc = 0.0f;
    #pragma unroll 8
    for (int k = 0; k < KN; k++) {
        int j = sj[k];
        float v = ai + g_ab[j*2*HD + HD + c] + sdd[k] * wc;
        acc += silu_f(v);
    }
    g_s[node*HD + c] = acc;
}

// ======== shared device helpers for the HMMA kernels (128 threads) ==========
// synchronous A stage: fp32 global -> hi/lo bf16 swizzled smem @ A_OFF
__device__ __forceinline__ void stage_A(char* smem, const float* __restrict__ A,
                                        int rowBase, int tid) {
    #pragma unroll
    for (int i = 0; i < 8; i++) {
        int id = tid + 128*i;               // 1024 chunks
        int r = id >> 4, ch = id & 15;
        const float* src = A + (size_t)(rowBase + r)*HD + ch*8;
        float4 a0 = *(const float4*)(src);
        float4 a1 = *(const float4*)(src + 4);
        uint4 hv, lv;
        split2(a0.x, a0.y, hv.x, lv.x);
        split2(a0.z, a0.w, hv.y, lv.y);
        split2(a1.x, a1.y, hv.z, lv.z);
        split2(a1.z, a1.w, hv.w, lv.w);
        uint32_t off = (uint32_t)r*256u + (((uint32_t)ch ^ (uint32_t)(r & 7)) << 4);
        *(uint4*)(smem + A_OFF + off) = hv;
        *(uint4*)(smem + A_OFF + 16384 + off) = lv;
    }
}
// async B stage into a B set at boff: [BH0, BL0, BH1, BL1] (16KB each)
__device__ __forceinline__ void stage_B_async(uint32_t sb, uint32_t boff,
                                              const __nv_bfloat16* __restrict__ Bh,
                                              const __nv_bfloat16* __restrict__ Bl,
                                              int tid) {
    #pragma unroll
    for (int i = 0; i < 8; i++) {
        int id = tid + 128*i;
        cpa16(sb + boff +         id*16, (const char*)Bh + id*16);
        cpa16(sb + boff + 16384 + id*16, (const char*)Bl + id*16);
        cpa16(sb + boff + 32768 + id*16, (const char*)Bh + 16384 + id*16);
        cpa16(sb + boff + 49152 + id*16, (const char*)Bl + 16384 + id*16);
    }
}
// async raw fp32 copy of a 64x128 slab into SRAW
__device__ __forceinline__ void stage_S_async(uint32_t sb, const float* __restrict__ S,
                                              int tid) {
    #pragma unroll
    for (int i = 0; i < 32; i++) {
        int id = tid + 128*i;               // 4096 chunks of 16B
        cpa16(sb + SRAW_OFF + id*16, (const char*)S + id*16);
    }
}
// convert SRAW (raw fp32) -> hi/lo bf16 swizzled smem @ A_OFF
__device__ __forceinline__ void conv_S_to_A(char* smem, int tid) {
    #pragma unroll
    for (int i = 0; i < 8; i++) {
        int id = tid + 128*i;
        int r = id >> 4, ch = id & 15;
        const float* src = (const float*)(smem + SRAW_OFF + r*512 + ch*32);
        float4 a0 = *(const float4*)(src);
        float4 a1 = *(const float4*)(src + 4);
        uint4 hv, lv;
        split2(a0.x, a0.y, hv.x, lv.x);
        split2(a0.z, a0.w, hv.y, lv.y);
        split2(a1.x, a1.y, hv.z, lv.z);
        split2(a1.z, a1.w, hv.w, lv.w);
        uint32_t off = (uint32_t)r*256u + (((uint32_t)ch ^ (uint32_t)(r & 7)) << 4);
        *(uint4*)(smem + A_OFF + off) = hv;
        *(uint4*)(smem + A_OFF + 16384 + off) = lv;
    }
}
// one full K=128 MMA pass (3-term split), A @ A_OFF, B set @ boff
__device__ __forceinline__ void mma_pass(uint32_t sb, uint32_t boff, float acc[2][8][4],
                                         uint32_t aBase0, uint32_t aBase1, int wn,
                                         uint32_t sw, int lrow, int lkoff) {
    const uint32_t sAH = sb + A_OFF;
    const uint32_t sAL = sb + A_OFF + 16384;
    const uint32_t sBH = sb + boff + (wn ? 32768u : 0u);
    const uint32_t sBL = sBH + 16384u;
    #pragma unroll
    for (int ks = 0; ks < 8; ks++) {
        uint32_t kc = (uint32_t)(ks*2 + lkoff);
        uint32_t koff = ((kc ^ sw) << 4);
        uint32_t ah[8], al[8];
        ldm4(ah[0], ah[1], ah[2], ah[3], sAH + aBase0 + koff);
        ldm4(ah[4], ah[5], ah[6], ah[7], sAH + aBase1 + koff);
        ldm4(al[0], al[1], al[2], al[3], sAL + aBase0 + koff);
        ldm4(al[4], al[5], al[6], al[7], sAL + aBase1 + koff);
        #pragma unroll
        for (int q = 0; q < 4; q++) {
            uint32_t bh[4], bl[4];
            uint32_t bBase = (uint32_t)(q*16 + lrow)*256u + koff;
            ldm4(bh[0], bh[1], bh[2], bh[3], sBH + bBase);
            ldm4(bl[0], bl[1], bl[2], bl[3], sBL + bBase);
            #pragma unroll
            for (int mi = 0; mi < 2; mi++) {
                uint32_t* a = ah + mi*4;
                uint32_t* c = al + mi*4;
                mma16816(acc[mi][2*q+0], a[0], a[1], a[2], a[3], bh[0], bh[2]);
                mma16816(acc[mi][2*q+1], a[0], a[1], a[2], a[3], bh[1], bh[3]);
                mma16816(acc[mi][2*q+0], a[0], a[1], a[2], a[3], bl[0], bl[2]);
                mma16816(acc[mi][2*q+1], a[0], a[1], a[2], a[3], bl[1], bl[3]);
                mma16816(acc[mi][2*q+0], c[0], c[1], c[2], c[3], bh[0], bh[2]);
                mma16816(acc[mi][2*q+1], c[0], c[1], c[2], c[3], bh[1], bh[3]);
            }
        }
    }
}

// ---------------- gemm1: ab = h @ [W1a|W1b] + [b1|0]  (BN=128, 4 warps) -----
__global__ void __launch_bounds__(128) gemm_tc(
    const float* __restrict__ A0,
    const __nv_bfloat16* __restrict__ B0h, const __nv_bfloat16* __restrict__ B0l,
    const float* __restrict__ bias,
    float* __restrict__ C, int N)
{
    extern __shared__ char smem[];
    uint32_t sb = smem_u32(smem);
    const int tid  = threadIdx.x;
    const int wid  = tid >> 5, lane = tid & 31;
    const int rowBase = blockIdx.x * 64;
    const int colBase = blockIdx.y * 128;
    const int wm = (wid & 1) * 32, wn = (wid >> 1);

    float acc[2][8][4];
    #pragma unroll
    for (int mi = 0; mi < 2; mi++)
        #pragma unroll
        for (int ni = 0; ni < 8; ni++)
            #pragma unroll
            for (int q = 0; q < 4; q++) acc[mi][ni][q] = 0.0f;

    const int lrow  = lane & 15;
    const int lkoff = lane >> 4;
    const uint32_t sw = (uint32_t)(lrow & 7);
    const uint32_t aBase0 = (uint32_t)(wm + lrow)*256u;
    const uint32_t aBase1 = (uint32_t)(wm + 16 + lrow)*256u;

    // async B copy overlaps the synchronous A convert
    stage_B_async(sb, B0_OFF, B0h + (blockIdx.y*2)*8192, B0l + (blockIdx.y*2)*8192, tid);
    CP_COMMIT();
    stage_A(smem, A0, rowBase, tid);
    CP_WAIT(0);
    __syncthreads();
    mma_pass(sb, B0_OFF, acc, aBase0, aBase1, wn, sw, lrow, lkoff);

    const int erow = lane >> 2;
    const int ecol = (lane & 3) * 2;
    #pragma unroll
    for (int mi = 0; mi < 2; mi++) {
        #pragma unroll
        for (int ni = 0; ni < 8; ni++) {
            int row = rowBase + wm + mi*16 + erow;
            int col = colBase + wn*64 + ni*8 + ecol;
            float bx = bias[col], by = bias[col+1];
            *(float2*)(C + (size_t)row*N + col) =
                make_float2(acc[mi][ni][0] + bx, acc[mi][ni][1] + by);
            *(float2*)(C + (size_t)(row+8)*N + col) =
                make_float2(acc[mi][ni][2] + bx, acc[mi][ni][3] + by);
        }
    }
}

// ---------------- gemm23: h += silu(h@W3a + s@w2p + b2p) @ W4 + b4 ----------
// grid (128): CTA owns 64 rows, full 128-col width, 4 warps.
// cp.async pipelining: s+B2b copy overlaps pass1; B3 copy overlaps conv+pass2.
__global__ void __launch_bounds__(128) gemm23_k(
    const float* __restrict__ Ah_, const float* __restrict__ As_,
    const __nv_bfloat16* __restrict__ B2ah, const __nv_bfloat16* __restrict__ B2al,
    const __nv_bfloat16* __restrict__ B2bh, const __nv_bfloat16* __restrict__ B2bl,
    const __nv_bfloat16* __restrict__ B3h,  const __nv_bfloat16* __restrict__ B3l,
    const float* __restrict__ b2p, const float* __restrict__ b4,
    float* __restrict__ H)
{
    extern __shared__ char smem[];
    uint32_t sb = smem_u32(smem);
    const int tid  = threadIdx.x;
    const int wid  = tid >> 5, lane = tid & 31;
    const int rowBase = blockIdx.x * 64;
    const int wm = (wid & 1) * 32, wn = (wid >> 1);

    float acc[2][8][4];
    #pragma unroll
    for (int mi = 0; mi < 2; mi++)
        #pragma unroll
        for (int ni = 0; ni < 8; ni++)
            #pragma unroll
            for (int q = 0; q < 4; q++) acc[mi][ni][q] = 0.0f;

    const int lrow  = lane & 15;
    const int lkoff = lane >> 4;
    const uint32_t sw = (uint32_t)(lrow & 7);
    const uint32_t aBase0 = (uint32_t)(wm + lrow)*256u;
    const uint32_t aBase1 = (uint32_t)(wm + 16 + lrow)*256u;
    const int erow = lane >> 2;
    const int ecol = (lane & 3) * 2;

    // group 1: B2a -> B0.  group 2: s(raw) -> SRAW, B2b -> B1.
    stage_B_async(sb, B0_OFF, B2ah, B2al, tid);
    CP_COMMIT();
    stage_S_async(sb, As_ + (size_t)rowBase*HD, tid);
    stage_B_async(sb, B1_OFF, B2bh, B2bl, tid);
    CP_COMMIT();
    // synchronous h convert overlaps both copies
    stage_A(smem, Ah_, rowBase, tid);
    CP_WAIT(1);                       // group 1 (B2a) complete
    __syncthreads();

    // ---- pass 1: h @ W3a ----
    mma_pass(sb, B0_OFF, acc, aBase0, aBase1, wn, sw, lrow, lkoff);
    __syncthreads();                  // all warps done with A(h) + B0

    // group 3: B3 -> B0 (overlaps conv + pass 2)
    stage_B_async(sb, B0_OFF, B3h, B3l, tid);
    CP_COMMIT();
    CP_WAIT(1);                       // group 2 (SRAW + B1) complete
    __syncthreads();
    conv_S_to_A(smem, tid);           // SRAW -> A (hi/lo swizzled), smem-to-smem
    __syncthreads();

    // ---- pass 2: + s @ w2p ----
    mma_pass(sb, B1_OFF, acc, aBase0, aBase1, wn, sw, lrow, lkoff);
    __syncthreads();                  // all warps done with A(s)
    CP_WAIT(0);                       // group 3 (B3) complete

    // ---- mid epilogue: p2 = silu(acc + b2p) -> smem A (swizzled hi/lo) ----
    #pragma unroll
    for (int mi = 0; mi < 2; mi++) {
        #pragma unroll
        for (int ni = 0; ni < 8; ni++) {
            int rl0 = wm + mi*16 + erow;
            int col = wn*64 + ni*8 + ecol;
            float bx = b2p[col], by = b2p[col+1];
            float v00 = silu_f(acc[mi][ni][0] + bx);
            float v01 = silu_f(acc[mi][ni][1] + by);
            float v10 = silu_f(acc[mi][ni][2] + bx);
            float v11 = silu_f(acc[mi][ni][3] + by);
            uint32_t hw, lw;
            split2(v00, v01, hw, lw);
            uint32_t o = tile_off(rl0, col);
            *(uint32_t*)(smem + A_OFF + o) = hw;
            *(uint32_t*)(smem + A_OFF + 16384 + o) = lw;
            split2(v10, v11, hw, lw);
            o = tile_off(rl0 + 8, col);
            *(uint32_t*)(smem + A_OFF + o) = hw;
            *(uint32_t*)(smem + A_OFF + 16384 + o) = lw;
            acc[mi][ni][0] = acc[mi][ni][1] = acc[mi][ni][2] = acc[mi][ni][3] = 0.0f;
        }
    }
    __syncthreads();                  // p2 writes + B3 visibility before pass 3

    // ---- pass 3: p2 @ W4 ----
    mma_pass(sb, B0_OFF, acc, aBase0, aBase1, wn, sw, lrow, lkoff);

    // ---- final epilogue: h += . + b4 ----
    #pragma unroll
    for (int mi = 0; mi < 2; mi++) {
        #pragma unroll
        for (int ni = 0; ni < 8; ni++) {
            int row = rowBase + wm + mi*16 + erow;
            int col = wn*64 + ni*8 + ecol;
            float bx = b4[col], by = b4[col+1];
            float* h0 = H + (size_t)row*HD + col;
            float* h1 = H + (size_t)(row+8)*HD + col;
            float2 e0 = *(float2*)h0;
            float2 e1 = *(float2*)h1;
            *(float2*)h0 = make_float2(acc[mi][ni][0] + bx + e0.x,
                                       acc[mi][ni][1] + by + e0.y);
            *(float2*)h1 = make_float2(acc[mi][ni][2] + bx + e1.x,
                                       acc[mi][ni][3] + by + e1.y);
        }
    }
}

// ---------------- final projection ------------------------------------------
__global__ void out_k(const float* __restrict__ ow, const float* __restrict__ ob,
                      float* __restrict__ out) {
    int t = blockIdx.x * blockDim.x + threadIdx.x;
    if (t >= NODES*OUTD) return;
    int node = t / OUTD, oc = t % OUTD;
    float acc = ob[oc];
    #pragma unroll 8
    for (int k = 0; k < HD; k++) acc += g_h[node*HD + k] * ow[k*OUTD + oc];
    out[t] = acc;
}

// ---------------------------------------------------------------------------
extern "C" void kernel_launch(void* const* d_in, const int* in_sizes, int n_in,
                              void* d_out, int out_size) {
    const float* x   = (const float*)d_in[0];
    const float* ew  = (const float*)d_in[1];
    const float* eb  = (const float*)d_in[2];
    const float* miw = (const float*)d_in[3];
    const float* mib = (const float*)d_in[4];
    const float* mow = (const float*)d_in[5];
    const float* mob = (const float*)d_in[6];
    const float* uiw = (const float*)d_in[7];
    const float* uib = (const float*)d_in[8];
    const float* uow = (const float*)d_in[9];
    const float* uob = (const float*)d_in[10];
    const float* ow  = (const float*)d_in[11];
    const float* ob  = (const float*)d_in[12];
    float* out = (float*)d_out;

    cudaFuncSetAttribute(gemm_tc,  cudaFuncAttributeMaxDynamicSharedMemorySize, SMEM_G1);
    cudaFuncSetAttribute(gemm23_k, cudaFuncAttributeMaxDynamicSharedMemorySize, SMEM_G23);

    float *ph, *pab, *ps, *pbbias, *pb2p;
    __nv_bfloat16 *pB1h, *pB1l, *pB2ah, *pB2al, *pB2bh, *pB2bl, *pB3h, *pB3l;
    cudaGetSymbolAddress((void**)&ph,     g_h);
    cudaGetSymbolAddress((void**)&pab,    g_ab);
    cudaGetSymbolAddress((void**)&ps,     g_s);
    cudaGetSymbolAddress((void**)&pbbias, g_bbias);
    cudaGetSymbolAddress((void**)&pb2p,   g_b2p);
    cudaGetSymbolAddress((void**)&pB1h,   g_B1h);
    cudaGetSymbolAddress((void**)&pB1l,   g_B1l);
    cudaGetSymbolAddress((void**)&pB2ah,  g_B2ah);
    cudaGetSymbolAddress((void**)&pB2al,  g_B2al);
    cudaGetSymbolAddress((void**)&pB2bh,  g_B2bh);
    cudaGetSymbolAddress((void**)&pB2bl,  g_B2bl);
    cudaGetSymbolAddress((void**)&pB3h,   g_B3h);
    cudaGetSymbolAddress((void**)&pB3l,   g_B3l);

    embed_k<<<NODES*HD/256, 256>>>(x, ew, eb);
    knn_k<<<NODES/4, 128>>>(x);
    {
        int total = NL*2*HD + NL*HD*HD + NL*HD;
        prep_k<<<(total + 255)/256, 256>>>(mib, mow, mob, uiw, uib);
        prep2_k<<<(NL*10*8192 + 255)/256, 256>>>(miw, uiw, uow);
    }

    for (int l = 0; l < NL; l++) {
        // [a|bb] = h @ [W1a|W1b] + [b1|0]   (8192 x 256)
        gemm_tc<<<dim3(128, 2), 128, SMEM_G1>>>(
            ph, pB1h + l*4*8192, pB1l + l*4*8192,
            pbbias + l*2*HD, pab, 2*HD);
        // s_i = sum_k silu(a_i + bb_j + d*w1c)
        edge_k<<<NODES, 128>>>(miw, l);
        // h += silu(h@W3a + s@w2p + b2p) @ W4 + b4   (fused gemm2+3)
        gemm23_k<<<dim3(128, 1), 128, SMEM_G23>>>(
            ph, ps,
            pB2ah + l*2*8192, pB2al + l*2*8192,
            pB2bh + l*2*8192, pB2bl + l*2*8192,
            pB3h + l*2*8192,  pB3l + l*2*8192,
            pb2p + l*HD, uob + l*HD, ph);
    }
    out_k<<<(NODES*OUTD + 255)/256, 256>>>(ow, ob, out);
}